// round 12
// baseline (speedup 1.0000x reference)
#include <cuda_runtime.h>
#include <math.h>

#define Bz 4
#define Nz 4096
#define Cz 64
#define Kz 16
#define EPSf 1e-5f
#define FLT_BIG 3.402823466e38f
#define FULLMASK 0xffffffffu

#define NWARP 12
#define MAIN_GRID 152
#define KWARPS 16          // queries per knn block

#define W_FLOATS 12864     // 3*4096 weights + 192 pe1 + 6*64 biases
#define MAIN_FLOATS (W_FLOATS + NWARP*2048)   // 37440 -> 149.76 KB

// qkv smem: xs [64][68] + 3 weight mats [64][68] = 4*4352 = 17408 floats (69.6KB)
#define QKV_FLOATS (4*64*68)
#define QKV_THREADS 512

// ---------------- scratch (device globals; no allocation allowed) ----------------
__device__ float g_q[Bz*Nz*Cz];
__device__ float g_k[Bz*Nz*Cz];
__device__ float g_v[Bz*Nz*Cz];
__device__ int   g_idx[Bz*Nz*Kz];
// folded params (weights in c-quad float4 layout: w[c4*256 + o*4 + j] = W[o][4c4+j])
__device__ float g_pe_w1f[Cz*3];
__device__ float g_b_pef[Cz];
__device__ float g_pe_w2q[Cz*Cz];
__device__ float g_pe_b2c[Cz];
__device__ float g_s0[Cz], g_b0[Cz];
__device__ float g_at_w1q[Cz*Cz];    // rows scaled by s1[o]
__device__ float g_bb1[Cz];
__device__ float g_at_w2q[Cz*Cz];
__device__ float g_at_b2c[Cz];

// packed f32x2 fma (FFMA2; only reachable via PTX)
__device__ __forceinline__ float2 fma2(float2 a, float2 b, float2 c) {
    unsigned long long A = *(unsigned long long*)&a;
    unsigned long long B = *(unsigned long long*)&b;
    unsigned long long C = *(unsigned long long*)&c;
    unsigned long long D;
    asm("fma.rn.f32x2 %0, %1, %2, %3;" : "=l"(D) : "l"(A), "l"(B), "l"(C));
    return *(float2*)&D;
}

// ---------------- kernel 1: qkv (blocks 0..255, 512thr) + fold (block 256) ----------------
__global__ __launch_bounds__(QKV_THREADS)
void qkv_fold_kernel(
    const float* __restrict__ x,
    const float* __restrict__ Wq, const float* __restrict__ bq,
    const float* __restrict__ Wk, const float* __restrict__ bk,
    const float* __restrict__ Wv, const float* __restrict__ bv,
    const float* __restrict__ pe_w1,
    const float* __restrict__ pbg, const float* __restrict__ pbb,
    const float* __restrict__ pbm, const float* __restrict__ pbv,
    const float* __restrict__ pe_w2, const float* __restrict__ pe_b2,
    const float* __restrict__ a0g, const float* __restrict__ a0b,
    const float* __restrict__ a0m, const float* __restrict__ a0v,
    const float* __restrict__ at_w1,
    const float* __restrict__ a1g, const float* __restrict__ a1b,
    const float* __restrict__ a1m, const float* __restrict__ a1v,
    const float* __restrict__ at_w2, const float* __restrict__ at_b2)
{
    extern __shared__ float dyn[];
    int t = threadIdx.x;

    if (blockIdx.x == Bz*(Nz/64)) {
        // ---- fold block ----
        __shared__ float s1sh[Cz];
        if (t < Cz) {
            float spe = pbg[t] * rsqrtf(pbv[t] + EPSf);
            g_b_pef[t] = pbb[t] - pbm[t] * spe;
            #pragma unroll
            for (int j = 0; j < 3; j++) g_pe_w1f[t*3+j] = pe_w1[t*3+j] * spe;
            g_pe_b2c[t] = pe_b2[t];
            float s0 = a0g[t] * rsqrtf(a0v[t] + EPSf);
            g_s0[t] = s0;
            g_b0[t] = a0b[t] - a0m[t] * s0;
            float s1 = a1g[t] * rsqrtf(a1v[t] + EPSf);
            s1sh[t] = s1;
            g_bb1[t] = a1b[t] - a1m[t] * s1;
            g_at_b2c[t] = at_b2[t];
        }
        __syncthreads();
        for (int i = t; i < 64*16; i += QKV_THREADS) {
            int o = i & 63, c4 = i >> 6;
            float s1v = s1sh[o];
            #pragma unroll
            for (int j = 0; j < 4; j++) {
                int d = c4*256 + o*4 + j;
                int s = o*Cz + 4*c4 + j;
                g_pe_w2q[d] = pe_w2[s];
                g_at_w1q[d] = at_w1[s] * s1v;
                g_at_w2q[d] = at_w2[s];
            }
        }
        return;
    }

    // ---- qkv blocks: x transposed [j][c] (68-pad), weights row-major [o][c] (68-pad) ----
    float* xs = dyn;             // [64 j][68]
    float* wq = xs + 64*68;      // [64 o][68]
    float* wk = wq + 64*68;
    float* wv = wk + 64*68;

    int b  = blockIdx.x >> 6;
    int n0 = (blockIdx.x & 63) * 64;

    for (int i = t; i < 4096; i += QKV_THREADS) {
        int o = i >> 6, c = i & 63;
        wq[o*68 + c] = Wq[i]; wk[o*68 + c] = Wk[i]; wv[o*68 + c] = Wv[i];
    }
    for (int i = t; i < 4096; i += QKV_THREADS) {
        int c = i >> 6, j = i & 63;
        xs[j*68 + c] = x[(b*Cz + c)*Nz + n0 + j];   // coalesced gmem read
    }
    __syncthreads();

    int o  = t & 63;
    int jg = t >> 6;                 // 0..7, 8 j each
    float bqo = bq[o], bko = bk[o], bvo = bv[o];
    const float4* wq4 = (const float4*)(wq + o*68);
    const float4* wk4 = (const float4*)(wk + o*68);
    const float4* wv4 = (const float4*)(wv + o*68);

    #pragma unroll 2
    for (int jj = 0; jj < 8; jj++) {
        int j = jg*8 + jj;
        const float4* xs4 = (const float4*)(xs + j*68);
        float2 aq01 = make_float2(0.f,0.f), aq23 = make_float2(0.f,0.f);
        float2 ak01 = make_float2(0.f,0.f), ak23 = make_float2(0.f,0.f);
        float2 av01 = make_float2(0.f,0.f), av23 = make_float2(0.f,0.f);
        #pragma unroll
        for (int c4 = 0; c4 < 16; c4++) {
            float4 xv = xs4[c4];
            float2 x01 = make_float2(xv.x, xv.y), x23 = make_float2(xv.z, xv.w);
            float4 w;
            w = wq4[c4];
            aq01 = fma2(make_float2(w.x,w.y), x01, aq01);
            aq23 = fma2(make_float2(w.z,w.w), x23, aq23);
            w = wk4[c4];
            ak01 = fma2(make_float2(w.x,w.y), x01, ak01);
            ak23 = fma2(make_float2(w.z,w.w), x23, ak23);
            w = wv4[c4];
            av01 = fma2(make_float2(w.x,w.y), x01, av01);
            av23 = fma2(make_float2(w.z,w.w), x23, av23);
        }
        int base = ((b*Nz) + n0 + j)*Cz + o;
        g_q[base] = ((aq01.x + aq01.y) + (aq23.x + aq23.y)) + bqo;
        g_k[base] = ((ak01.x + ak01.y) + (ak23.x + ak23.y)) + bko;
        g_v[base] = ((av01.x + av01.y) + (av23.x + av23.y)) + bvo;
    }
}

// ---------------- kernel 2: KNN — 4 candidates/lane, (-2x) staging, per-hit recheck ----------------
// Staged as (-2x,-2y,-2z,ssq|INF). Power-of-2 scaling commutes exactly with RN rounding,
// so dot' = sum((-2x_m)*x_n) == -2 * (reference's rounded dot chain) bit-exactly, and
// d2 = (qsq+ssqm) + dot' matches the reference ranking identically.
// grid = B * (Nz/KWARPS) = 1024 blocks, 512 threads (16 warps = 16 queries), smem 64KB.
__global__ __launch_bounds__(KWARPS*32)
void knn_kernel(const float* __restrict__ p)
{
    extern __shared__ float dyn[];
    float4* p4 = (float4*)dyn;   // [4096] (-2x,-2y,-2z, ssq | +INF if invalid)

    int t = threadIdx.x, lane = t & 31, warp = t >> 5;
    int blksPerB = Nz / KWARPS;           // 256
    int b = blockIdx.x / blksPerB;
    int n = (blockIdx.x - b*blksPerB) * KWARPS + warp;

    const float INF = __int_as_float(0x7f800000);
    const float* pb3 = p + b*Nz*3;
    for (int m = t; m < Nz; m += KWARPS*32) {
        float x0 = __ldg(pb3 + 3*m), y0 = __ldg(pb3 + 3*m + 1), z0 = __ldg(pb3 + 3*m + 2);
        // ssq rounded exactly as the reference: (x*x + y*y) + z*z; +INF marks invalid point
        float ss = __fadd_rn(__fadd_rn(__fmul_rn(x0,x0), __fmul_rn(y0,y0)), __fmul_rn(z0,z0));
        bool invalid = (x0 == 0.f) && (y0 == 0.f) && (z0 == 0.f);
        p4[m] = make_float4(-2.0f*x0, -2.0f*y0, -2.0f*z0, invalid ? INF : ss);
    }
    __syncthreads();

    float4 q4 = p4[n];
    float qx = -0.5f * q4.x, qy = -0.5f * q4.y, qz = -0.5f * q4.z;   // exact recovery
    float qsq = __fadd_rn(__fadd_rn(__fmul_rn(qx,qx), __fmul_rn(qy,qy)), __fmul_rn(qz,qz));

    // warp-distributed sorted list (ascending by (d2, idx)); lanes 0..15 = top-16
    float lv = FLT_BIG;
    int   li = 0x7fffffff;
    float kthv = FLT_BIG;
    int   kthi = 0x7fffffff;

    // uniform sorted-shift insert of (v,i), with per-hit recheck + kth refresh
    auto insert = [&](unsigned mask, float d2, int m) {
        while (mask) {
            int src = __ffs(mask) - 1;
            mask &= mask - 1;
            float v = __shfl_sync(FULLMASK, d2, src);
            int   i = __shfl_sync(FULLMASK, m, src);
            if ((v < kthv) || (v == kthv && i < kthi)) {   // skip hits made obsolete this batch
                float upv = __shfl_up_sync(FULLMASK, lv, 1);
                int   upi = __shfl_up_sync(FULLMASK, li, 1);
                bool gt  = (lv > v)  || (lv == v  && li > i);
                bool gtu = (lane > 0) && ((upv > v) || (upv == v && upi > i));
                if (gt) {
                    lv = gtu ? upv : v;
                    li = gtu ? upi : i;
                }
                kthv = __shfl_sync(FULLMASK, lv, 15);
                kthi = __shfl_sync(FULLMASK, li, 15);
            }
        }
    };

    // d2(m) = (qsq + ssq_m) + ((-2x_m)*qx + (-2y_m)*qy + (-2z_m)*qz), un-contracted chain
    auto cand_d2 = [&](const float4& c) {
        float dotp = __fadd_rn(__fadd_rn(__fmul_rn(c.x,qx), __fmul_rn(c.y,qy)), __fmul_rn(c.z,qz));
        return __fadd_rn(__fadd_rn(qsq, c.w), dotp);
    };

    for (int base = 0; base < Nz; base += 128) {
        int m0 = base + lane, m1 = m0 + 32, m2 = m0 + 64, m3 = m0 + 96;
        float d2a = cand_d2(p4[m0]);
        float d2b = cand_d2(p4[m1]);
        float d2c = cand_d2(p4[m2]);
        float d2d = cand_d2(p4[m3]);

        unsigned mask0 = __ballot_sync(FULLMASK, (d2a < kthv) || (d2a == kthv && m0 < kthi));
        unsigned mask1 = __ballot_sync(FULLMASK, (d2b < kthv) || (d2b == kthv && m1 < kthi));
        unsigned mask2 = __ballot_sync(FULLMASK, (d2c < kthv) || (d2c == kthv && m2 < kthi));
        unsigned mask3 = __ballot_sync(FULLMASK, (d2d < kthv) || (d2d == kthv && m3 < kthi));
        if (mask0 | mask1 | mask2 | mask3) {
            insert(mask0, d2a, m0);
            insert(mask1, d2b, m1);
            insert(mask2, d2c, m2);
            insert(mask3, d2d, m3);
        }
    }

    if (lane < Kz) g_idx[(b*Nz + n)*Kz + lane] = li;
}

// ---------------- warp-solo gemvs (single pass, acc[16][2] — needs ~168 regs, NO spills) ----------------
__device__ __forceinline__ void gemv_core(
    const float* __restrict__ Wq, const float* __restrict__ inb,
    int lane, float2 acc[16][2])
{
    const float4* W4 = (const float4*)Wq;
    #pragma unroll
    for (int r = 0; r < 16; r++) { acc[r][0] = make_float2(0.f,0.f); acc[r][1] = make_float2(0.f,0.f); }
    #pragma unroll
    for (int c4 = 0; c4 < 16; c4++) {
        float4 wA = W4[c4*64 + lane];
        float4 wB = W4[c4*64 + lane + 32];
        float2 wA01 = make_float2(wA.x, wA.y), wA23 = make_float2(wA.z, wA.w);
        float2 wB01 = make_float2(wB.x, wB.y), wB23 = make_float2(wB.z, wB.w);
        #pragma unroll
        for (int r = 0; r < 16; r++) {
            float4 xv = *(const float4*)&inb[r*64 + 4*c4];    // broadcast
            float2 x01 = make_float2(xv.x, xv.y), x23 = make_float2(xv.z, xv.w);
            acc[r][0] = fma2(wA01, x01, acc[r][0]);
            acc[r][0] = fma2(wA23, x23, acc[r][0]);
            acc[r][1] = fma2(wB01, x01, acc[r][1]);
            acc[r][1] = fma2(wB23, x23, acc[r][1]);
        }
    }
}

__device__ __forceinline__ void gemv_regs(
    const float* __restrict__ Wq, const float* __restrict__ inb,
    const float* __restrict__ bias, int lane, float o0[16], float o1[16])
{
    float2 acc[16][2];
    gemv_core(Wq, inb, lane, acc);
    float ba = bias[lane], bb = bias[lane + 32];
    #pragma unroll
    for (int r = 0; r < 16; r++) {
        o0[r] = (acc[r][0].x + acc[r][0].y) + ba;
        o1[r] = (acc[r][1].x + acc[r][1].y) + bb;
    }
}

__device__ __forceinline__ void gemv_smem_relu(
    const float* __restrict__ Wq, const float* __restrict__ inb,
    float* __restrict__ outb, const float* __restrict__ bias, int lane)
{
    float2 acc[16][2];
    gemv_core(Wq, inb, lane, acc);
    float ba = bias[lane], bb = bias[lane + 32];
    #pragma unroll
    for (int r = 0; r < 16; r++) {
        outb[r*64 + lane]      = fmaxf((acc[r][0].x + acc[r][0].y) + ba, 0.f);
        outb[r*64 + lane + 32] = fmaxf((acc[r][1].x + acc[r][1].y) + bb, 0.f);
    }
}

// ---------------- kernel 3: warp-per-point fused MLP pipeline, zero barriers ----------------
// grid = 152 persistent blocks, 384 threads (12 independent warps), smem ~150KB.
__global__ __launch_bounds__(NWARP*32, 1)
void main_kernel(const float* __restrict__ p, float* __restrict__ out)
{
    extern __shared__ float dyn[];
    float* w2t = dyn;              // pe_w2 c-quad       4096
    float* w1a = w2t + 4096;       // at_w1 c-quad       4096
    float* w2a = w1a + 4096;       // at_w2 c-quad       4096
    float* pe1 = w2a + 4096;       // 192
    float* bpe = pe1 + 192;        // 64
    float* pb2 = bpe + 64;
    float* s0  = pb2 + 64;
    float* b0  = s0  + 64;
    float* bb1 = b0  + 64;
    float* ab2 = bb1 + 64;
    float* bufs = ab2 + 64;        // [NWARP][2][1024]

    int t = threadIdx.x, lane = t & 31, warp = t >> 5;

    for (int i = t; i < 4096; i += NWARP*32) {
        w2t[i] = g_pe_w2q[i];
        w1a[i] = g_at_w1q[i];
        w2a[i] = g_at_w2q[i];
    }
    if (t < 192) pe1[t] = g_pe_w1f[t];
    if (t >= 192 && t < 256) {
        int c = t - 192;
        bpe[c] = g_b_pef[c]; pb2[c] = g_pe_b2c[c];
        s0[c]  = g_s0[c];    b0[c]  = g_b0[c];
        bb1[c] = g_bb1[c];   ab2[c] = g_at_b2c[c];
    }
    __syncthreads();

    int c0 = lane, c1 = lane + 32;
    float pa0 = pe1[c0*3], pa1 = pe1[c0*3+1], pa2 = pe1[c0*3+2];
    float pq0 = pe1[c1*3], pq1 = pe1[c1*3+1], pq2 = pe1[c1*3+2];
    float bpa = bpe[c0], bpb = bpe[c1];
    float s0a = s0[c0],  s0b = s0[c1];
    float b0a = b0[c0],  b0b = b0[c1];

    float* B0 = bufs + warp*2048;        // h / a1
    float* B2 = B0 + 1024;               // a3

    const int stride = MAIN_GRID * NWARP;
    for (int g = blockIdx.x * NWARP + warp; g < Bz*Nz; g += stride) {
        int b = g >> 12, n = g & 4095;
        const float* pb3 = p + b*Nz*3;
        int bN64 = b*Nz*Cz;

        int idv[Kz];
        #pragma unroll
        for (int k = 0; k < Kz; k++) idv[k] = __ldg(g_idx + g*Kz + k);

        float psx = __ldg(p + g*3), psy = __ldg(p + g*3 + 1), psz = __ldg(p + g*3 + 2);

        // h[k][c] = relu(pe_w1f @ (p - pn) + b_pef)
        #pragma unroll
        for (int k = 0; k < Kz; k++) {
            int id = idv[k];
            float rx = psx - __ldg(pb3 + id*3);
            float ry = psy - __ldg(pb3 + id*3 + 1);
            float rz = psz - __ldg(pb3 + id*3 + 2);
            float h0 = fmaf(pa0, rx, fmaf(pa1, ry, fmaf(pa2, rz, bpa)));
            float h1 = fmaf(pq0, rx, fmaf(pq1, ry, fmaf(pq2, rz, bpb)));
            B0[k*64 + c0] = fmaxf(h0, 0.f);
            B0[k*64 + c1] = fmaxf(h1, 0.f);
        }
        __syncwarp();

        // n_r in registers (lane owns c0, c1 per k)
        float nr0[Kz], nr1[Kz];
        gemv_regs(w2t, B0, pb2, lane, nr0, nr1);
        __syncwarp();

        // a1[k][c] = relu((q - n_k + n_r)*s0 + b0) -> B0
        float qa = __ldg(g_q + g*Cz + c0), qb = __ldg(g_q + g*Cz + c1);
        #pragma unroll
        for (int k = 0; k < Kz; k++) {
            int base = bN64 + idv[k]*Cz;
            float nk0 = __ldg(g_k + base + c0);
            float nk1 = __ldg(g_k + base + c1);
            float a0x = fmaf(qa - nk0 + nr0[k], s0a, b0a);
            float a1x = fmaf(qb - nk1 + nr1[k], s0b, b0b);
            B0[k*64 + c0] = fmaxf(a0x, 0.f);
            B0[k*64 + c1] = fmaxf(a1x, 0.f);
        }
        __syncwarp();

        // a3[k][o] = relu(at_w1' @ a1 + bb1) -> B2
        gemv_smem_relu(w1a, B0, B2, bb1, lane);
        __syncwarp();

        // a4 in registers
        float a40[Kz], a41[Kz];
        gemv_regs(w2a, B2, ab2, lane, a40, a41);

        // softmax over k + aggregate, entirely in registers (mask all-true)
        float* outp = out + Bz*Nz*3 + (b*Cz)*Nz + n;
        {
            float mx0 = -FLT_BIG, mx1 = -FLT_BIG;
            #pragma unroll
            for (int k = 0; k < Kz; k++) { mx0 = fmaxf(mx0, a40[k]); mx1 = fmaxf(mx1, a41[k]); }
            float sA = 0.f, sB = 0.f;
            #pragma unroll
            for (int k = 0; k < Kz; k++) {
                a40[k] = __expf(a40[k] - mx0); sA += a40[k];
                a41[k] = __expf(a41[k] - mx1); sB += a41[k];
            }
            float invA = 1.f / sA, invB = 1.f / sB;
            float y0 = 0.f, y1 = 0.f;
            #pragma unroll
            for (int k = 0; k < Kz; k++) {
                int base = bN64 + idv[k]*Cz;
                float v0 = __ldg(g_v + base + c0);
                float v1 = __ldg(g_v + base + c1);
                y0 = fmaf(a40[k]*invA, v0 + nr0[k], y0);
                y1 = fmaf(a41[k]*invB, v1 + nr1[k], y1);
            }
            outp[c0*Nz] = y0;
            outp[c1*Nz] = y1;
        }
        __syncwarp();
    }
}

// ---------------- launch ----------------
extern "C" void kernel_launch(void* const* d_in, const int* in_sizes, int n_in,
                              void* d_out, int out_size)
{
    const float* p     = (const float*)d_in[0];
    const float* x     = (const float*)d_in[1];
    // d_in[2] = mask, all-true by construction -> unused
    const float* Wq    = (const float*)d_in[3];
    const float* bq    = (const float*)d_in[4];
    const float* Wk    = (const float*)d_in[5];
    const float* bk    = (const float*)d_in[6];
    const float* Wv    = (const float*)d_in[7];
    const float* bv    = (const float*)d_in[8];
    const float* pe_w1 = (const float*)d_in[9];
    const float* pbg   = (const float*)d_in[10];
    const float* pbb   = (const float*)d_in[11];
    const float* pbm   = (const float*)d_in[12];
    const float* pbv   = (const float*)d_in[13];
    const float* pe_w2 = (const float*)d_in[14];
    const float* pe_b2 = (const float*)d_in[15];
    const float* a0g   = (const float*)d_in[16];
    const float* a0b   = (const float*)d_in[17];
    const float* a0m   = (const float*)d_in[18];
    const float* a0v   = (const float*)d_in[19];
    const float* at_w1 = (const float*)d_in[20];
    const float* a1g   = (const float*)d_in[21];
    const float* a1b   = (const float*)d_in[22];
    const float* a1m   = (const float*)d_in[23];
    const float* a1v   = (const float*)d_in[24];
    const float* at_w2 = (const float*)d_in[25];
    const float* at_b2 = (const float*)d_in[26];

    float* out = (float*)d_out;

    const int QKV_SMEM  = QKV_FLOATS * (int)sizeof(float);            // ~69.6KB
    const int KNN_SMEM  = Nz * 4 * (int)sizeof(float);                // 64KB
    const int MAIN_SMEM = MAIN_FLOATS * (int)sizeof(float);           // ~150KB

    cudaFuncSetAttribute(qkv_fold_kernel, cudaFuncAttributeMaxDynamicSharedMemorySize, QKV_SMEM);
    cudaFuncSetAttribute(knn_kernel,      cudaFuncAttributeMaxDynamicSharedMemorySize, KNN_SMEM);
    cudaFuncSetAttribute(main_kernel,     cudaFuncAttributeMaxDynamicSharedMemorySize, MAIN_SMEM);

    // output = (p, y): p first
    cudaMemcpyAsync(out, p, (size_t)Bz*Nz*3*sizeof(float), cudaMemcpyDeviceToDevice);

    qkv_fold_kernel<<<Bz*(Nz/64) + 1, QKV_THREADS, QKV_SMEM>>>(
        x, Wq, bq, Wk, bk, Wv, bv,
        pe_w1, pbg, pbb, pbm, pbv, pe_w2, pe_b2,
        a0g, a0b, a0m, a0v, at_w1,
        a1g, a1b, a1m, a1v, at_w2, at_b2);

    knn_kernel<<<Bz*(Nz/KWARPS), KWARPS*32, KNN_SMEM>>>(p);

    main_kernel<<<MAIN_GRID, NWARP*32, MAIN_SMEM>>>(p, out);
}

// round 13
// speedup vs baseline: 1.2435x; 1.2435x over previous
#include <cuda_runtime.h>
#include <math.h>

#define Bz 4
#define Nz 4096
#define Cz 64
#define Kz 16
#define EPSf 1e-5f
#define FLT_BIG 3.402823466e38f
#define FULLMASK 0xffffffffu

#define NWARP 14
#define MAIN_GRID 152
#define KWARPS 16          // queries per knn block

#define W_FLOATS 12864     // 3*4096 weights + 192 pe1 + 6*64 biases
#define MAIN_FLOATS (W_FLOATS + NWARP*3072)   // 55872 -> 223.5 KB

// qkv smem: xs [64][68] + 3 weight mats [64][68] = 4*4352 = 17408 floats (69.6KB)
#define QKV_FLOATS (4*64*68)

// ---------------- scratch (device globals; no allocation allowed) ----------------
__device__ float g_q[Bz*Nz*Cz];
__device__ float g_k[Bz*Nz*Cz];
__device__ float g_v[Bz*Nz*Cz];
__device__ int   g_idx[Bz*Nz*Kz];
// folded params (weights in c-quad float4 layout: w[c4*256 + o*4 + j] = W[o][4c4+j])
__device__ float g_pe_w1f[Cz*3];
__device__ float g_b_pef[Cz];
__device__ float g_pe_w2q[Cz*Cz];
__device__ float g_pe_b2c[Cz];
__device__ float g_s0[Cz], g_b0[Cz];
__device__ float g_at_w1q[Cz*Cz];    // rows scaled by s1[o]
__device__ float g_bb1[Cz];
__device__ float g_at_w2q[Cz*Cz];
__device__ float g_at_b2c[Cz];

// packed f32x2 fma (FFMA2; only reachable via PTX)
__device__ __forceinline__ float2 fma2(float2 a, float2 b, float2 c) {
    unsigned long long A = *(unsigned long long*)&a;
    unsigned long long B = *(unsigned long long*)&b;
    unsigned long long C = *(unsigned long long*)&c;
    unsigned long long D;
    asm("fma.rn.f32x2 %0, %1, %2, %3;" : "=l"(D) : "l"(A), "l"(B), "l"(C));
    return *(float2*)&D;
}

// ---------------- kernel 1: qkv (blocks 0..255, float4/fma2) + fold (block 256) ----------------
// R11-measured 38.0us config: 256 threads, unroll 4, no reg cap (252 regs, 1 block/SM, NO spills).
__global__ __launch_bounds__(256)
void qkv_fold_kernel(
    const float* __restrict__ x,
    const float* __restrict__ Wq, const float* __restrict__ bq,
    const float* __restrict__ Wk, const float* __restrict__ bk,
    const float* __restrict__ Wv, const float* __restrict__ bv,
    const float* __restrict__ pe_w1,
    const float* __restrict__ pbg, const float* __restrict__ pbb,
    const float* __restrict__ pbm, const float* __restrict__ pbv,
    const float* __restrict__ pe_w2, const float* __restrict__ pe_b2,
    const float* __restrict__ a0g, const float* __restrict__ a0b,
    const float* __restrict__ a0m, const float* __restrict__ a0v,
    const float* __restrict__ at_w1,
    const float* __restrict__ a1g, const float* __restrict__ a1b,
    const float* __restrict__ a1m, const float* __restrict__ a1v,
    const float* __restrict__ at_w2, const float* __restrict__ at_b2)
{
    extern __shared__ float dyn[];
    int t = threadIdx.x;

    if (blockIdx.x == Bz*(Nz/64)) {
        // ---- fold block ----
        __shared__ float s1sh[Cz];
        if (t < Cz) {
            float spe = pbg[t] * rsqrtf(pbv[t] + EPSf);
            g_b_pef[t] = pbb[t] - pbm[t] * spe;
            #pragma unroll
            for (int j = 0; j < 3; j++) g_pe_w1f[t*3+j] = pe_w1[t*3+j] * spe;
            g_pe_b2c[t] = pe_b2[t];
            float s0 = a0g[t] * rsqrtf(a0v[t] + EPSf);
            g_s0[t] = s0;
            g_b0[t] = a0b[t] - a0m[t] * s0;
            float s1 = a1g[t] * rsqrtf(a1v[t] + EPSf);
            s1sh[t] = s1;
            g_bb1[t] = a1b[t] - a1m[t] * s1;
            g_at_b2c[t] = at_b2[t];
        }
        __syncthreads();
        for (int i = t; i < 64*16; i += blockDim.x) {
            int o = i & 63, c4 = i >> 6;
            float s1v = s1sh[o];
            #pragma unroll
            for (int j = 0; j < 4; j++) {
                int d = c4*256 + o*4 + j;
                int s = o*Cz + 4*c4 + j;
                g_pe_w2q[d] = pe_w2[s];
                g_at_w1q[d] = at_w1[s] * s1v;
                g_at_w2q[d] = at_w2[s];
            }
        }
        return;
    }

    // ---- qkv blocks: x transposed [j][c] (68-pad), weights row-major [o][c] (68-pad) ----
    float* xs = dyn;             // [64 j][68]
    float* wq = xs + 64*68;      // [64 o][68]
    float* wk = wq + 64*68;
    float* wv = wk + 64*68;

    int b  = blockIdx.x >> 6;
    int n0 = (blockIdx.x & 63) * 64;

    for (int i = t; i < 4096; i += 256) {
        int o = i >> 6, c = i & 63;
        wq[o*68 + c] = Wq[i]; wk[o*68 + c] = Wk[i]; wv[o*68 + c] = Wv[i];
    }
    for (int i = t; i < 4096; i += 256) {
        int c = i >> 6, j = i & 63;
        xs[j*68 + c] = x[(b*Cz + c)*Nz + n0 + j];   // coalesced gmem read
    }
    __syncthreads();

    int o  = t & 63;
    int jg = t >> 6;                 // 0..3, 16 j each
    float bqo = bq[o], bko = bk[o], bvo = bv[o];
    const float4* wq4 = (const float4*)(wq + o*68);
    const float4* wk4 = (const float4*)(wk + o*68);
    const float4* wv4 = (const float4*)(wv + o*68);

    #pragma unroll 4
    for (int jj = 0; jj < 16; jj++) {
        int j = jg*16 + jj;
        const float4* xs4 = (const float4*)(xs + j*68);
        float2 aq01 = make_float2(0.f,0.f), aq23 = make_float2(0.f,0.f);
        float2 ak01 = make_float2(0.f,0.f), ak23 = make_float2(0.f,0.f);
        float2 av01 = make_float2(0.f,0.f), av23 = make_float2(0.f,0.f);
        #pragma unroll
        for (int c4 = 0; c4 < 16; c4++) {
            float4 xv = xs4[c4];
            float2 x01 = make_float2(xv.x, xv.y), x23 = make_float2(xv.z, xv.w);
            float4 w;
            w = wq4[c4];
            aq01 = fma2(make_float2(w.x,w.y), x01, aq01);
            aq23 = fma2(make_float2(w.z,w.w), x23, aq23);
            w = wk4[c4];
            ak01 = fma2(make_float2(w.x,w.y), x01, ak01);
            ak23 = fma2(make_float2(w.z,w.w), x23, ak23);
            w = wv4[c4];
            av01 = fma2(make_float2(w.x,w.y), x01, av01);
            av23 = fma2(make_float2(w.z,w.w), x23, av23);
        }
        int base = ((b*Nz) + n0 + j)*Cz + o;
        g_q[base] = ((aq01.x + aq01.y) + (aq23.x + aq23.y)) + bqo;
        g_k[base] = ((ak01.x + ak01.y) + (ak23.x + ak23.y)) + bko;
        g_v[base] = ((av01.x + av01.y) + (av23.x + av23.y)) + bvo;
    }
}

// ---------------- kernel 2: KNN — 2 candidates/lane, INF-validity, per-hit recheck ----------------
// R11-measured (~85us) config. grid = 1024, 512 threads (16 warps = 16 queries), smem 64KB.
__global__ __launch_bounds__(KWARPS*32)
void knn_kernel(const float* __restrict__ p)
{
    extern __shared__ float dyn[];
    float4* p4 = (float4*)dyn;   // [4096] (x,y,z,ssq | +INF if invalid)

    int t = threadIdx.x, lane = t & 31, warp = t >> 5;
    int blksPerB = Nz / KWARPS;           // 256
    int b = blockIdx.x / blksPerB;
    int n = (blockIdx.x - b*blksPerB) * KWARPS + warp;

    const float INF = __int_as_float(0x7f800000);
    const float* pb3 = p + b*Nz*3;
    for (int m = t; m < Nz; m += KWARPS*32) {
        float x0 = __ldg(pb3 + 3*m), y0 = __ldg(pb3 + 3*m + 1), z0 = __ldg(pb3 + 3*m + 2);
        // ssq rounded exactly as the reference: (x*x + y*y) + z*z; +INF marks invalid point
        float ss = __fadd_rn(__fadd_rn(__fmul_rn(x0,x0), __fmul_rn(y0,y0)), __fmul_rn(z0,z0));
        bool invalid = (x0 == 0.f) && (y0 == 0.f) && (z0 == 0.f);
        p4[m] = make_float4(x0, y0, z0, invalid ? INF : ss);
    }
    __syncthreads();

    float4 q4 = p4[n];
    float qx = q4.x, qy = q4.y, qz = q4.z;
    float qsq = __fadd_rn(__fadd_rn(__fmul_rn(qx,qx), __fmul_rn(qy,qy)), __fmul_rn(qz,qz));

    // warp-distributed sorted list (ascending by (d2, idx)); lanes 0..15 = top-16
    float lv = FLT_BIG;
    int   li = 0x7fffffff;
    float kthv = FLT_BIG;
    int   kthi = 0x7fffffff;

    // uniform sorted-shift insert of (v,i), with per-hit recheck + kth refresh
    auto insert = [&](unsigned mask, float d2, int m) {
        while (mask) {
            int src = __ffs(mask) - 1;
            mask &= mask - 1;
            float v = __shfl_sync(FULLMASK, d2, src);
            int   i = __shfl_sync(FULLMASK, m, src);
            if ((v < kthv) || (v == kthv && i < kthi)) {   // skip hits made obsolete this batch
                float upv = __shfl_up_sync(FULLMASK, lv, 1);
                int   upi = __shfl_up_sync(FULLMASK, li, 1);
                bool gt  = (lv > v)  || (lv == v  && li > i);
                bool gtu = (lane > 0) && ((upv > v) || (upv == v && upi > i));
                if (gt) {
                    lv = gtu ? upv : v;
                    li = gtu ? upi : i;
                }
                kthv = __shfl_sync(FULLMASK, lv, 15);
                kthi = __shfl_sync(FULLMASK, li, 15);
            }
        }
    };

    for (int base = 0; base < Nz; base += 64) {
        int m0 = base + lane;
        int m1 = m0 + 32;
        float4 ca = p4[m0];
        float4 cb = p4[m1];
        // d2 = (sq_n + sq_m) - 2*dot, un-contracted fp to match reference ranking
        float dota = __fadd_rn(__fadd_rn(__fmul_rn(ca.x,qx), __fmul_rn(ca.y,qy)), __fmul_rn(ca.z,qz));
        float d2a  = __fadd_rn(__fadd_rn(qsq, ca.w), -__fmul_rn(2.0f, dota));
        float dotb = __fadd_rn(__fadd_rn(__fmul_rn(cb.x,qx), __fmul_rn(cb.y,qy)), __fmul_rn(cb.z,qz));
        float d2b  = __fadd_rn(__fadd_rn(qsq, cb.w), -__fmul_rn(2.0f, dotb));

        bool hit0 = (d2a < kthv) || (d2a == kthv && m0 < kthi);
        bool hit1 = (d2b < kthv) || (d2b == kthv && m1 < kthi);
        unsigned mask0 = __ballot_sync(FULLMASK, hit0);
        unsigned mask1 = __ballot_sync(FULLMASK, hit1);
        if (mask0 | mask1) {
            insert(mask0, d2a, m0);
            insert(mask1, d2b, m1);
        }
    }

    if (lane < Kz) g_idx[(b*Nz + n)*Kz + lane] = li;
}

// ---------------- warp-solo gemvs (single pass, acc[16][2]) ----------------
__device__ __forceinline__ void gemv_core(
    const float* __restrict__ Wq, const float* __restrict__ inb,
    int lane, float2 acc[16][2])
{
    const float4* W4 = (const float4*)Wq;
    #pragma unroll
    for (int r = 0; r < 16; r++) { acc[r][0] = make_float2(0.f,0.f); acc[r][1] = make_float2(0.f,0.f); }
    #pragma unroll
    for (int c4 = 0; c4 < 16; c4++) {
        float4 wA = W4[c4*64 + lane];
        float4 wB = W4[c4*64 + lane + 32];
        float2 wA01 = make_float2(wA.x, wA.y), wA23 = make_float2(wA.z, wA.w);
        float2 wB01 = make_float2(wB.x, wB.y), wB23 = make_float2(wB.z, wB.w);
        #pragma unroll
        for (int r = 0; r < 16; r++) {
            float4 xv = *(const float4*)&inb[r*64 + 4*c4];    // broadcast
            float2 x01 = make_float2(xv.x, xv.y), x23 = make_float2(xv.z, xv.w);
            acc[r][0] = fma2(wA01, x01, acc[r][0]);
            acc[r][0] = fma2(wA23, x23, acc[r][0]);
            acc[r][1] = fma2(wB01, x01, acc[r][1]);
            acc[r][1] = fma2(wB23, x23, acc[r][1]);
        }
    }
}

// out to registers (no relu) — used for a4 only
__device__ __forceinline__ void gemv_regs(
    const float* __restrict__ Wq, const float* __restrict__ inb,
    const float* __restrict__ bias, int lane, float o0[16], float o1[16])
{
    float2 acc[16][2];
    gemv_core(Wq, inb, lane, acc);
    float ba = bias[lane], bb = bias[lane + 32];
    #pragma unroll
    for (int r = 0; r < 16; r++) {
        o0[r] = (acc[r][0].x + acc[r][0].y) + ba;
        o1[r] = (acc[r][1].x + acc[r][1].y) + bb;
    }
}

// out to smem, optional relu
template<bool DORELU>
__device__ __forceinline__ void gemv_smem(
    const float* __restrict__ Wq, const float* __restrict__ inb,
    float* __restrict__ outb, const float* __restrict__ bias, int lane)
{
    float2 acc[16][2];
    gemv_core(Wq, inb, lane, acc);
    float ba = bias[lane], bb = bias[lane + 32];
    #pragma unroll
    for (int r = 0; r < 16; r++) {
        float r0 = (acc[r][0].x + acc[r][0].y) + ba;
        float r1 = (acc[r][1].x + acc[r][1].y) + bb;
        if (DORELU) { r0 = fmaxf(r0, 0.f); r1 = fmaxf(r1, 0.f); }
        outb[r*64 + lane]      = r0;
        outb[r*64 + lane + 32] = r1;
    }
}

// ---------------- kernel 3: warp-per-point fused MLP pipeline, zero barriers ----------------
// 14 warps (448 thr): nr lives in smem (B1) instead of registers so demand (~115 regs)
// stays under the 146-reg ceiling — NO spills (R8 lesson). smem ~223.5KB, 1 block/SM.
__global__ __launch_bounds__(NWARP*32, 1)
void main_kernel(const float* __restrict__ p, float* __restrict__ out)
{
    extern __shared__ float dyn[];
    float* w2t = dyn;              // pe_w2 c-quad       4096
    float* w1a = w2t + 4096;       // at_w1 c-quad       4096
    float* w2a = w1a + 4096;       // at_w2 c-quad       4096
    float* pe1 = w2a + 4096;       // 192
    float* bpe = pe1 + 192;        // 64
    float* pb2 = bpe + 64;
    float* s0  = pb2 + 64;
    float* b0  = s0  + 64;
    float* bb1 = b0  + 64;
    float* ab2 = bb1 + 64;
    float* bufs = ab2 + 64;        // [NWARP][3][1024]

    int t = threadIdx.x, lane = t & 31, warp = t >> 5;

    for (int i = t; i < 4096; i += NWARP*32) {
        w2t[i] = g_pe_w2q[i];
        w1a[i] = g_at_w1q[i];
        w2a[i] = g_at_w2q[i];
    }
    if (t < 192) pe1[t] = g_pe_w1f[t];
    if (t >= 192 && t < 256) {
        int c = t - 192;
        bpe[c] = g_b_pef[c]; pb2[c] = g_pe_b2c[c];
        s0[c]  = g_s0[c];    b0[c]  = g_b0[c];
        bb1[c] = g_bb1[c];   ab2[c] = g_at_b2c[c];
    }
    __syncthreads();

    int c0 = lane, c1 = lane + 32;
    float pa0 = pe1[c0*3], pa1 = pe1[c0*3+1], pa2 = pe1[c0*3+2];
    float pq0 = pe1[c1*3], pq1 = pe1[c1*3+1], pq2 = pe1[c1*3+2];
    float bpa = bpe[c0], bpb = bpe[c1];
    float s0a = s0[c0],  s0b = s0[c1];
    float b0a = b0[c0],  b0b = b0[c1];

    float* B0 = bufs + warp*3072;        // h / a1
    float* B1 = B0 + 1024;               // nr (smem — frees 32 regs vs register version)
    float* B2 = B1 + 1024;               // a3

    const int stride = MAIN_GRID * NWARP;
    for (int g = blockIdx.x * NWARP + warp; g < Bz*Nz; g += stride) {
        int b = g >> 12, n = g & 4095;
        const float* pb3 = p + b*Nz*3;
        int bN64 = b*Nz*Cz;

        int idv[Kz];
        #pragma unroll
        for (int k = 0; k < Kz; k++) idv[k] = __ldg(g_idx + g*Kz + k);

        float psx = __ldg(p + g*3), psy = __ldg(p + g*3 + 1), psz = __ldg(p + g*3 + 2);

        // h[k][c] = relu(pe_w1f @ (p - pn) + b_pef)
        #pragma unroll
        for (int k = 0; k < Kz; k++) {
            int id = idv[k];
            float rx = psx - __ldg(pb3 + id*3);
            float ry = psy - __ldg(pb3 + id*3 + 1);
            float rz = psz - __ldg(pb3 + id*3 + 2);
            float h0 = fmaf(pa0, rx, fmaf(pa1, ry, fmaf(pa2, rz, bpa)));
            float h1 = fmaf(pq0, rx, fmaf(pq1, ry, fmaf(pq2, rz, bpb)));
            B0[k*64 + c0] = fmaxf(h0, 0.f);
            B0[k*64 + c1] = fmaxf(h1, 0.f);
        }
        __syncwarp();

        // n_r[k][o] -> B1 (smem)
        gemv_smem<false>(w2t, B0, B1, pb2, lane);
        __syncwarp();

        // a1[k][c] = relu((q - n_k + n_r)*s0 + b0) -> B0
        float qa = __ldg(g_q + g*Cz + c0), qb = __ldg(g_q + g*Cz + c1);
        #pragma unroll
        for (int k = 0; k < Kz; k++) {
            int base = bN64 + idv[k]*Cz;
            float nk0 = __ldg(g_k + base + c0);
            float nk1 = __ldg(g_k + base + c1);
            float a0x = fmaf(qa - nk0 + B1[k*64 + c0], s0a, b0a);
            float a1x = fmaf(qb - nk1 + B1[k*64 + c1], s0b, b0b);
            B0[k*64 + c0] = fmaxf(a0x, 0.f);
            B0[k*64 + c1] = fmaxf(a1x, 0.f);
        }
        __syncwarp();

        // a3[k][o] = relu(at_w1' @ a1 + bb1) -> B2
        gemv_smem<true>(w1a, B0, B2, bb1, lane);
        __syncwarp();

        // a4 in registers
        float a40[Kz], a41[Kz];
        gemv_regs(w2a, B2, ab2, lane, a40, a41);

        // softmax over k + aggregate (mask all-true); nr re-read from B1
        float* outp = out + Bz*Nz*3 + (b*Cz)*Nz + n;
        {
            float mx0 = -FLT_BIG, mx1 = -FLT_BIG;
            #pragma unroll
            for (int k = 0; k < Kz; k++) { mx0 = fmaxf(mx0, a40[k]); mx1 = fmaxf(mx1, a41[k]); }
            float sA = 0.f, sB = 0.f;
            #pragma unroll
            for (int k = 0; k < Kz; k++) {
                a40[k] = __expf(a40[k] - mx0); sA += a40[k];
                a41[k] = __expf(a41[k] - mx1); sB += a41[k];
            }
            float invA = 1.f / sA, invB = 1.f / sB;
            float y0 = 0.f, y1 = 0.f;
            #pragma unroll
            for (int k = 0; k < Kz; k++) {
                int base = bN64 + idv[k]*Cz;
                float v0 = __ldg(g_v + base + c0);
                float v1 = __ldg(g_v + base + c1);
                y0 = fmaf(a40[k]*invA, v0 + B1[k*64 + c0], y0);
                y1 = fmaf(a41[k]*invB, v1 + B1[k*64 + c1], y1);
            }
            outp[c0*Nz] = y0;
            outp[c1*Nz] = y1;
        }
        __syncwarp();
    }
}

// ---------------- launch ----------------
extern "C" void kernel_launch(void* const* d_in, const int* in_sizes, int n_in,
                              void* d_out, int out_size)
{
    const float* p     = (const float*)d_in[0];
    const float* x     = (const float*)d_in[1];
    // d_in[2] = mask, all-true by construction -> unused
    const float* Wq    = (const float*)d_in[3];
    const float* bq    = (const float*)d_in[4];
    const float* Wk    = (const float*)d_in[5];
    const float* bk    = (const float*)d_in[6];
    const float* Wv    = (const float*)d_in[7];
    const float* bv    = (const float*)d_in[8];
    const float* pe_w1 = (const float*)d_in[9];
    const float* pbg   = (const float*)d_in[10];
    const float* pbb   = (const float*)d_in[11];
    const float* pbm   = (const float*)d_in[12];
    const float* pbv   = (const float*)d_in[13];
    const float* pe_w2 = (const float*)d_in[14];
    const float* pe_b2 = (const float*)d_in[15];
    const float* a0g   = (const float*)d_in[16];
    const float* a0b   = (const float*)d_in[17];
    const float* a0m   = (const float*)d_in[18];
    const float* a0v   = (const float*)d_in[19];
    const float* at_w1 = (const float*)d_in[20];
    const float* a1g   = (const float*)d_in[21];
    const float* a1b   = (const float*)d_in[22];
    const float* a1m   = (const float*)d_in[23];
    const float* a1v   = (const float*)d_in[24];
    const float* at_w2 = (const float*)d_in[25];
    const float* at_b2 = (const float*)d_in[26];

    float* out = (float*)d_out;

    const int QKV_SMEM  = QKV_FLOATS * (int)sizeof(float);            // ~69.6KB
    const int KNN_SMEM  = Nz * 4 * (int)sizeof(float);                // 64KB
    const int MAIN_SMEM = MAIN_FLOATS * (int)sizeof(float);           // ~223.5KB

    cudaFuncSetAttribute(qkv_fold_kernel, cudaFuncAttributeMaxDynamicSharedMemorySize, QKV_SMEM);
    cudaFuncSetAttribute(knn_kernel,      cudaFuncAttributeMaxDynamicSharedMemorySize, KNN_SMEM);
    cudaFuncSetAttribute(main_kernel,     cudaFuncAttributeMaxDynamicSharedMemorySize, MAIN_SMEM);

    // output = (p, y): p first
    cudaMemcpyAsync(out, p, (size_t)Bz*Nz*3*sizeof(float), cudaMemcpyDeviceToDevice);

    qkv_fold_kernel<<<Bz*(Nz/64) + 1, 256, QKV_SMEM>>>(
        x, Wq, bq, Wk, bk, Wv, bv,
        pe_w1, pbg, pbb, pbm, pbv, pe_w2, pe_b2,
        a0g, a0b, a0m, a0v, at_w1,
        a1g, a1b, a1m, a1v, at_w2, at_b2);

    knn_kernel<<<Bz*(Nz/KWARPS), KWARPS*32, KNN_SMEM>>>(p);

    main_kernel<<<MAIN_GRID, NWARP*32, MAIN_SMEM>>>(p, out);
}

// round 14
// speedup vs baseline: 1.3093x; 1.0529x over previous
#include <cuda_runtime.h>
#include <math.h>

#define Bz 4
#define Nz 4096
#define Cz 64
#define Kz 16
#define EPSf 1e-5f
#define FLT_BIG 3.402823466e38f
#define FULLMASK 0xffffffffu

#define NWARP 12
#define MAIN_GRID 152
#define KWARPS 32          // queries per knn block (1024 threads)

#define W_FLOATS 12864     // 3*4096 weights + 192 pe1 + 6*64 biases
#define MAIN_FLOATS (W_FLOATS + NWARP*2048)   // 37440 -> 149.76 KB

// qkv smem: xs [64][68] + 3 weight mats [64][68] = 4*4352 = 17408 floats (69.6KB)
#define QKV_FLOATS (4*64*68)

// ---------------- scratch (device globals; no allocation allowed) ----------------
__device__ float g_q[Bz*Nz*Cz];
__device__ float g_k[Bz*Nz*Cz];
__device__ float g_v[Bz*Nz*Cz];
__device__ int   g_idx[Bz*Nz*Kz];
// folded params (weights in c-quad float4 layout: w[c4*256 + o*4 + j] = W[o][4c4+j])
__device__ float g_pe_w1f[Cz*3];
__device__ float g_b_pef[Cz];
__device__ float g_pe_w2q[Cz*Cz];
__device__ float g_pe_b2c[Cz];
__device__ float g_s0[Cz], g_b0[Cz];
__device__ float g_at_w1q[Cz*Cz];    // rows scaled by s1[o]
__device__ float g_bb1[Cz];
__device__ float g_at_w2q[Cz*Cz];
__device__ float g_at_b2c[Cz];

// packed f32x2 fma (FFMA2; only reachable via PTX)
__device__ __forceinline__ float2 fma2(float2 a, float2 b, float2 c) {
    unsigned long long A = *(unsigned long long*)&a;
    unsigned long long B = *(unsigned long long*)&b;
    unsigned long long C = *(unsigned long long*)&c;
    unsigned long long D;
    asm("fma.rn.f32x2 %0, %1, %2, %3;" : "=l"(D) : "l"(A), "l"(B), "l"(C));
    return *(float2*)&D;
}

// ---------------- kernel 1: qkv (blocks 0..255, float4/fma2) + fold (block 256) ----------------
// R11-measured 38.0us config: 256 threads, unroll 4, no reg cap (252 regs, 1 block/SM, NO spills).
__global__ __launch_bounds__(256)
void qkv_fold_kernel(
    const float* __restrict__ x,
    const float* __restrict__ Wq, const float* __restrict__ bq,
    const float* __restrict__ Wk, const float* __restrict__ bk,
    const float* __restrict__ Wv, const float* __restrict__ bv,
    const float* __restrict__ pe_w1,
    const float* __restrict__ pbg, const float* __restrict__ pbb,
    const float* __restrict__ pbm, const float* __restrict__ pbv,
    const float* __restrict__ pe_w2, const float* __restrict__ pe_b2,
    const float* __restrict__ a0g, const float* __restrict__ a0b,
    const float* __restrict__ a0m, const float* __restrict__ a0v,
    const float* __restrict__ at_w1,
    const float* __restrict__ a1g, const float* __restrict__ a1b,
    const float* __restrict__ a1m, const float* __restrict__ a1v,
    const float* __restrict__ at_w2, const float* __restrict__ at_b2)
{
    extern __shared__ float dyn[];
    int t = threadIdx.x;

    if (blockIdx.x == Bz*(Nz/64)) {
        // ---- fold block ----
        __shared__ float s1sh[Cz];
        if (t < Cz) {
            float spe = pbg[t] * rsqrtf(pbv[t] + EPSf);
            g_b_pef[t] = pbb[t] - pbm[t] * spe;
            #pragma unroll
            for (int j = 0; j < 3; j++) g_pe_w1f[t*3+j] = pe_w1[t*3+j] * spe;
            g_pe_b2c[t] = pe_b2[t];
            float s0 = a0g[t] * rsqrtf(a0v[t] + EPSf);
            g_s0[t] = s0;
            g_b0[t] = a0b[t] - a0m[t] * s0;
            float s1 = a1g[t] * rsqrtf(a1v[t] + EPSf);
            s1sh[t] = s1;
            g_bb1[t] = a1b[t] - a1m[t] * s1;
            g_at_b2c[t] = at_b2[t];
        }
        __syncthreads();
        for (int i = t; i < 64*16; i += blockDim.x) {
            int o = i & 63, c4 = i >> 6;
            float s1v = s1sh[o];
            #pragma unroll
            for (int j = 0; j < 4; j++) {
                int d = c4*256 + o*4 + j;
                int s = o*Cz + 4*c4 + j;
                g_pe_w2q[d] = pe_w2[s];
                g_at_w1q[d] = at_w1[s] * s1v;
                g_at_w2q[d] = at_w2[s];
            }
        }
        return;
    }

    // ---- qkv blocks: x transposed [j][c] (68-pad), weights row-major [o][c] (68-pad) ----
    float* xs = dyn;             // [64 j][68]
    float* wq = xs + 64*68;      // [64 o][68]
    float* wk = wq + 64*68;
    float* wv = wk + 64*68;

    int b  = blockIdx.x >> 6;
    int n0 = (blockIdx.x & 63) * 64;

    for (int i = t; i < 4096; i += 256) {
        int o = i >> 6, c = i & 63;
        wq[o*68 + c] = Wq[i]; wk[o*68 + c] = Wk[i]; wv[o*68 + c] = Wv[i];
    }
    for (int i = t; i < 4096; i += 256) {
        int c = i >> 6, j = i & 63;
        xs[j*68 + c] = x[(b*Cz + c)*Nz + n0 + j];   // coalesced gmem read
    }
    __syncthreads();

    int o  = t & 63;
    int jg = t >> 6;                 // 0..3, 16 j each
    float bqo = bq[o], bko = bk[o], bvo = bv[o];
    const float4* wq4 = (const float4*)(wq + o*68);
    const float4* wk4 = (const float4*)(wk + o*68);
    const float4* wv4 = (const float4*)(wv + o*68);

    #pragma unroll 4
    for (int jj = 0; jj < 16; jj++) {
        int j = jg*16 + jj;
        const float4* xs4 = (const float4*)(xs + j*68);
        float2 aq01 = make_float2(0.f,0.f), aq23 = make_float2(0.f,0.f);
        float2 ak01 = make_float2(0.f,0.f), ak23 = make_float2(0.f,0.f);
        float2 av01 = make_float2(0.f,0.f), av23 = make_float2(0.f,0.f);
        #pragma unroll
        for (int c4 = 0; c4 < 16; c4++) {
            float4 xv = xs4[c4];
            float2 x01 = make_float2(xv.x, xv.y), x23 = make_float2(xv.z, xv.w);
            float4 w;
            w = wq4[c4];
            aq01 = fma2(make_float2(w.x,w.y), x01, aq01);
            aq23 = fma2(make_float2(w.z,w.w), x23, aq23);
            w = wk4[c4];
            ak01 = fma2(make_float2(w.x,w.y), x01, ak01);
            ak23 = fma2(make_float2(w.z,w.w), x23, ak23);
            w = wv4[c4];
            av01 = fma2(make_float2(w.x,w.y), x01, av01);
            av23 = fma2(make_float2(w.z,w.w), x23, av23);
        }
        int base = ((b*Nz) + n0 + j)*Cz + o;
        g_q[base] = ((aq01.x + aq01.y) + (aq23.x + aq23.y)) + bqo;
        g_k[base] = ((ak01.x + ak01.y) + (ak23.x + ak23.y)) + bko;
        g_v[base] = ((av01.x + av01.y) + (av23.x + av23.y)) + bvo;
    }
}

// ---------------- kernel 2: KNN — 2 candidates/lane, INF-validity, per-hit recheck ----------------
// R11 scan/insert code unchanged; KWARPS 16->32 (1024-thr blocks, 512 blocks):
// halves total tile-staging work and raises warps/SM (2 blocks x 32 warps = 64).
__global__ __launch_bounds__(KWARPS*32)
void knn_kernel(const float* __restrict__ p)
{
    extern __shared__ float dyn[];
    float4* p4 = (float4*)dyn;   // [4096] (x,y,z,ssq | +INF if invalid)

    int t = threadIdx.x, lane = t & 31, warp = t >> 5;
    int blksPerB = Nz / KWARPS;           // 128
    int b = blockIdx.x / blksPerB;
    int n = (blockIdx.x - b*blksPerB) * KWARPS + warp;

    const float INF = __int_as_float(0x7f800000);
    const float* pb3 = p + b*Nz*3;
    for (int m = t; m < Nz; m += KWARPS*32) {
        float x0 = __ldg(pb3 + 3*m), y0 = __ldg(pb3 + 3*m + 1), z0 = __ldg(pb3 + 3*m + 2);
        // ssq rounded exactly as the reference: (x*x + y*y) + z*z; +INF marks invalid point
        float ss = __fadd_rn(__fadd_rn(__fmul_rn(x0,x0), __fmul_rn(y0,y0)), __fmul_rn(z0,z0));
        bool invalid = (x0 == 0.f) && (y0 == 0.f) && (z0 == 0.f);
        p4[m] = make_float4(x0, y0, z0, invalid ? INF : ss);
    }
    __syncthreads();

    float4 q4 = p4[n];
    float qx = q4.x, qy = q4.y, qz = q4.z;
    float qsq = __fadd_rn(__fadd_rn(__fmul_rn(qx,qx), __fmul_rn(qy,qy)), __fmul_rn(qz,qz));

    // warp-distributed sorted list (ascending by (d2, idx)); lanes 0..15 = top-16
    float lv = FLT_BIG;
    int   li = 0x7fffffff;
    float kthv = FLT_BIG;
    int   kthi = 0x7fffffff;

    // uniform sorted-shift insert of (v,i), with per-hit recheck + kth refresh
    auto insert = [&](unsigned mask, float d2, int m) {
        while (mask) {
            int src = __ffs(mask) - 1;
            mask &= mask - 1;
            float v = __shfl_sync(FULLMASK, d2, src);
            int   i = __shfl_sync(FULLMASK, m, src);
            if ((v < kthv) || (v == kthv && i < kthi)) {   // skip hits made obsolete this batch
                float upv = __shfl_up_sync(FULLMASK, lv, 1);
                int   upi = __shfl_up_sync(FULLMASK, li, 1);
                bool gt  = (lv > v)  || (lv == v  && li > i);
                bool gtu = (lane > 0) && ((upv > v) || (upv == v && upi > i));
                if (gt) {
                    lv = gtu ? upv : v;
                    li = gtu ? upi : i;
                }
                kthv = __shfl_sync(FULLMASK, lv, 15);
                kthi = __shfl_sync(FULLMASK, li, 15);
            }
        }
    };

    for (int base = 0; base < Nz; base += 64) {
        int m0 = base + lane;
        int m1 = m0 + 32;
        float4 ca = p4[m0];
        float4 cb = p4[m1];
        // d2 = (sq_n + sq_m) - 2*dot, un-contracted fp to match reference ranking
        float dota = __fadd_rn(__fadd_rn(__fmul_rn(ca.x,qx), __fmul_rn(ca.y,qy)), __fmul_rn(ca.z,qz));
        float d2a  = __fadd_rn(__fadd_rn(qsq, ca.w), -__fmul_rn(2.0f, dota));
        float dotb = __fadd_rn(__fadd_rn(__fmul_rn(cb.x,qx), __fmul_rn(cb.y,qy)), __fmul_rn(cb.z,qz));
        float d2b  = __fadd_rn(__fadd_rn(qsq, cb.w), -__fmul_rn(2.0f, dotb));

        bool hit0 = (d2a < kthv) || (d2a == kthv && m0 < kthi);
        bool hit1 = (d2b < kthv) || (d2b == kthv && m1 < kthi);
        unsigned mask0 = __ballot_sync(FULLMASK, hit0);
        unsigned mask1 = __ballot_sync(FULLMASK, hit1);
        if (mask0 | mask1) {
            insert(mask0, d2a, m0);
            insert(mask1, d2b, m1);
        }
    }

    if (lane < Kz) g_idx[(b*Nz + n)*Kz + lane] = li;
}

// ---------------- warp-solo gemvs (single pass, acc[16][2] — ~168 regs, NO spills) ----------------
__device__ __forceinline__ void gemv_core(
    const float* __restrict__ Wq, const float* __restrict__ inb,
    int lane, float2 acc[16][2])
{
    const float4* W4 = (const float4*)Wq;
    #pragma unroll
    for (int r = 0; r < 16; r++) { acc[r][0] = make_float2(0.f,0.f); acc[r][1] = make_float2(0.f,0.f); }
    #pragma unroll
    for (int c4 = 0; c4 < 16; c4++) {
        float4 wA = W4[c4*64 + lane];
        float4 wB = W4[c4*64 + lane + 32];
        float2 wA01 = make_float2(wA.x, wA.y), wA23 = make_float2(wA.z, wA.w);
        float2 wB01 = make_float2(wB.x, wB.y), wB23 = make_float2(wB.z, wB.w);
        #pragma unroll
        for (int r = 0; r < 16; r++) {
            float4 xv = *(const float4*)&inb[r*64 + 4*c4];    // broadcast
            float2 x01 = make_float2(xv.x, xv.y), x23 = make_float2(xv.z, xv.w);
            acc[r][0] = fma2(wA01, x01, acc[r][0]);
            acc[r][0] = fma2(wA23, x23, acc[r][0]);
            acc[r][1] = fma2(wB01, x01, acc[r][1]);
            acc[r][1] = fma2(wB23, x23, acc[r][1]);
        }
    }
}

__device__ __forceinline__ void gemv_regs(
    const float* __restrict__ Wq, const float* __restrict__ inb,
    const float* __restrict__ bias, int lane, float o0[16], float o1[16])
{
    float2 acc[16][2];
    gemv_core(Wq, inb, lane, acc);
    float ba = bias[lane], bb = bias[lane + 32];
    #pragma unroll
    for (int r = 0; r < 16; r++) {
        o0[r] = (acc[r][0].x + acc[r][0].y) + ba;
        o1[r] = (acc[r][1].x + acc[r][1].y) + bb;
    }
}

__device__ __forceinline__ void gemv_smem_relu(
    const float* __restrict__ Wq, const float* __restrict__ inb,
    float* __restrict__ outb, const float* __restrict__ bias, int lane)
{
    float2 acc[16][2];
    gemv_core(Wq, inb, lane, acc);
    float ba = bias[lane], bb = bias[lane + 32];
    #pragma unroll
    for (int r = 0; r < 16; r++) {
        outb[r*64 + lane]      = fmaxf((acc[r][0].x + acc[r][0].y) + ba, 0.f);
        outb[r*64 + lane + 32] = fmaxf((acc[r][1].x + acc[r][1].y) + bb, 0.f);
    }
}

// ---------------- kernel 3: warp-per-point fused MLP pipeline, zero barriers ----------------
// R11-measured config: 152 persistent blocks, 384 threads (12 warps), nr/a4 in registers,
// 168 regs (full RF), smem ~150KB. Measured local optimum — do not perturb.
__global__ __launch_bounds__(NWARP*32, 1)
void main_kernel(const float* __restrict__ p, float* __restrict__ out)
{
    extern __shared__ float dyn[];
    float* w2t = dyn;              // pe_w2 c-quad       4096
    float* w1a = w2t + 4096;       // at_w1 c-quad       4096
    float* w2a = w1a + 4096;       // at_w2 c-quad       4096
    float* pe1 = w2a + 4096;       // 192
    float* bpe = pe1 + 192;        // 64
    float* pb2 = bpe + 64;
    float* s0  = pb2 + 64;
    float* b0  = s0  + 64;
    float* bb1 = b0  + 64;
    float* ab2 = bb1 + 64;
    float* bufs = ab2 + 64;        // [NWARP][2][1024]

    int t = threadIdx.x, lane = t & 31, warp = t >> 5;

    for (int i = t; i < 4096; i += NWARP*32) {
        w2t[i] = g_pe_w2q[i];
        w1a[i] = g_at_w1q[i];
        w2a[i] = g_at_w2q[i];
    }
    if (t < 192) pe1[t] = g_pe_w1f[t];
    if (t >= 192 && t < 256) {
        int c = t - 192;
        bpe[c] = g_b_pef[c]; pb2[c] = g_pe_b2c[c];
        s0[c]  = g_s0[c];    b0[c]  = g_b0[c];
        bb1[c] = g_bb1[c];   ab2[c] = g_at_b2c[c];
    }
    __syncthreads();

    int c0 = lane, c1 = lane + 32;
    float pa0 = pe1[c0*3], pa1 = pe1[c0*3+1], pa2 = pe1[c0*3+2];
    float pq0 = pe1[c1*3], pq1 = pe1[c1*3+1], pq2 = pe1[c1*3+2];
    float bpa = bpe[c0], bpb = bpe[c1];
    float s0a = s0[c0],  s0b = s0[c1];
    float b0a = b0[c0],  b0b = b0[c1];

    float* B0 = bufs + warp*2048;        // h / a1
    float* B2 = B0 + 1024;               // a3

    const int stride = MAIN_GRID * NWARP;
    for (int g = blockIdx.x * NWARP + warp; g < Bz*Nz; g += stride) {
        int b = g >> 12, n = g & 4095;
        const float* pb3 = p + b*Nz*3;
        int bN64 = b*Nz*Cz;

        int idv[Kz];
        #pragma unroll
        for (int k = 0; k < Kz; k++) idv[k] = __ldg(g_idx + g*Kz + k);

        float psx = __ldg(p + g*3), psy = __ldg(p + g*3 + 1), psz = __ldg(p + g*3 + 2);

        // h[k][c] = relu(pe_w1f @ (p - pn) + b_pef)
        #pragma unroll
        for (int k = 0; k < Kz; k++) {
            int id = idv[k];
            float rx = psx - __ldg(pb3 + id*3);
            float ry = psy - __ldg(pb3 + id*3 + 1);
            float rz = psz - __ldg(pb3 + id*3 + 2);
            float h0 = fmaf(pa0, rx, fmaf(pa1, ry, fmaf(pa2, rz, bpa)));
            float h1 = fmaf(pq0, rx, fmaf(pq1, ry, fmaf(pq2, rz, bpb)));
            B0[k*64 + c0] = fmaxf(h0, 0.f);
            B0[k*64 + c1] = fmaxf(h1, 0.f);
        }
        __syncwarp();

        // n_r in registers (lane owns c0, c1 per k)
        float nr0[Kz], nr1[Kz];
        gemv_regs(w2t, B0, pb2, lane, nr0, nr1);
        __syncwarp();

        // a1[k][c] = relu((q - n_k + n_r)*s0 + b0) -> B0
        float qa = __ldg(g_q + g*Cz + c0), qb = __ldg(g_q + g*Cz + c1);
        #pragma unroll
        for (int k = 0; k < Kz; k++) {
            int base = bN64 + idv[k]*Cz;
            float nk0 = __ldg(g_k + base + c0);
            float nk1 = __ldg(g_k + base + c1);
            float a0x = fmaf(qa - nk0 + nr0[k], s0a, b0a);
            float a1x = fmaf(qb - nk1 + nr1[k], s0b, b0b);
            B0[k*64 + c0] = fmaxf(a0x, 0.f);
            B0[k*64 + c1] = fmaxf(a1x, 0.f);
        }
        __syncwarp();

        // a3[k][o] = relu(at_w1' @ a1 + bb1) -> B2
        gemv_smem_relu(w1a, B0, B2, bb1, lane);
        __syncwarp();

        // a4 in registers
        float a40[Kz], a41[Kz];
        gemv_regs(w2a, B2, ab2, lane, a40, a41);

        // softmax over k + aggregate, entirely in registers (mask all-true)
        float* outp = out + Bz*Nz*3 + (b*Cz)*Nz + n;
        {
            float mx0 = -FLT_BIG, mx1 = -FLT_BIG;
            #pragma unroll
            for (int k = 0; k < Kz; k++) { mx0 = fmaxf(mx0, a40[k]); mx1 = fmaxf(mx1, a41[k]); }
            float sA = 0.f, sB = 0.f;
            #pragma unroll
            for (int k = 0; k < Kz; k++) {
                a40[k] = __expf(a40[k] - mx0); sA += a40[k];
                a41[k] = __expf(a41[k] - mx1); sB += a41[k];
            }
            float invA = 1.f / sA, invB = 1.f / sB;
            float y0 = 0.f, y1 = 0.f;
            #pragma unroll
            for (int k = 0; k < Kz; k++) {
                int base = bN64 + idv[k]*Cz;
                float v0 = __ldg(g_v + base + c0);
                float v1 = __ldg(g_v + base + c1);
                y0 = fmaf(a40[k]*invA, v0 + nr0[k], y0);
                y1 = fmaf(a41[k]*invB, v1 + nr1[k], y1);
            }
            outp[c0*Nz] = y0;
            outp[c1*Nz] = y1;
        }
        __syncwarp();
    }
}

// ---------------- launch ----------------
extern "C" void kernel_launch(void* const* d_in, const int* in_sizes, int n_in,
                              void* d_out, int out_size)
{
    const float* p     = (const float*)d_in[0];
    const float* x     = (const float*)d_in[1];
    // d_in[2] = mask, all-true by construction -> unused
    const float* Wq    = (const float*)d_in[3];
    const float* bq    = (const float*)d_in[4];
    const float* Wk    = (const float*)d_in[5];
    const float* bk    = (const float*)d_in[6];
    const float* Wv    = (const float*)d_in[7];
    const float* bv    = (const float*)d_in[8];
    const float* pe_w1 = (const float*)d_in[9];
    const float* pbg   = (const float*)d_in[10];
    const float* pbb   = (const float*)d_in[11];
    const float* pbm   = (const float*)d_in[12];
    const float* pbv   = (const float*)d_in[13];
    const float* pe_w2 = (const float*)d_in[14];
    const float* pe_b2 = (const float*)d_in[15];
    const float* a0g   = (const float*)d_in[16];
    const float* a0b   = (const float*)d_in[17];
    const float* a0m   = (const float*)d_in[18];
    const float* a0v   = (const float*)d_in[19];
    const float* at_w1 = (const float*)d_in[20];
    const float* a1g   = (const float*)d_in[21];
    const float* a1b   = (const float*)d_in[22];
    const float* a1m   = (const float*)d_in[23];
    const float* a1v   = (const float*)d_in[24];
    const float* at_w2 = (const float*)d_in[25];
    const float* at_b2 = (const float*)d_in[26];

    float* out = (float*)d_out;

    const int QKV_SMEM  = QKV_FLOATS * (int)sizeof(float);            // ~69.6KB
    const int KNN_SMEM  = Nz * 4 * (int)sizeof(float);                // 64KB
    const int MAIN_SMEM = MAIN_FLOATS * (int)sizeof(float);           // ~150KB

    cudaFuncSetAttribute(qkv_fold_kernel, cudaFuncAttributeMaxDynamicSharedMemorySize, QKV_SMEM);
    cudaFuncSetAttribute(knn_kernel,      cudaFuncAttributeMaxDynamicSharedMemorySize, KNN_SMEM);
    cudaFuncSetAttribute(main_kernel,     cudaFuncAttributeMaxDynamicSharedMemorySize, MAIN_SMEM);

    // output = (p, y): p first
    cudaMemcpyAsync(out, p, (size_t)Bz*Nz*3*sizeof(float), cudaMemcpyDeviceToDevice);

    qkv_fold_kernel<<<Bz*(Nz/64) + 1, 256, QKV_SMEM>>>(
        x, Wq, bq, Wk, bk, Wv, bv,
        pe_w1, pbg, pbb, pbm, pbv, pe_w2, pe_b2,
        a0g, a0b, a0m, a0v, at_w1,
        a1g, a1b, a1m, a1v, at_w2, at_b2);

    knn_kernel<<<Bz*(Nz/KWARPS), KWARPS*32, KNN_SMEM>>>(p);

    main_kernel<<<MAIN_GRID, NWARP*32, MAIN_SMEM>>>(p, out);
}

// round 15
// speedup vs baseline: 1.3561x; 1.0357x over previous
#include <cuda_runtime.h>
#include <math.h>

#define Bz 4
#define Nz 4096
#define Cz 64
#define Kz 16
#define EPSf 1e-5f
#define FLT_BIG 3.402823466e38f
#define FULLMASK 0xffffffffu

#define NWARP 12
#define MAIN_GRID 152
#define KWARPS 16          // queries per knn block (R11-measured optimum)

#define W_FLOATS 12864     // 3*4096 weights + 192 pe1 + 6*64 biases
#define MAIN_FLOATS (W_FLOATS + NWARP*2048)   // 37440 -> 149.76 KB

// qkv smem: xs [64][68] + 3 weight mats [64][68] = 4*4352 = 17408 floats (69.6KB)
#define QKV_FLOATS (4*64*68)

// kernel-1 grid: [0,256) qkv, 256 fold, [257, 269) p->out copy
#define QKV_BLOCKS (Bz*(Nz/64))     // 256
#define COPY_BLOCKS 12              // 49152 floats / (256 thr * 16) = 12
#define K1_GRID (QKV_BLOCKS + 1 + COPY_BLOCKS)

// ---------------- scratch (device globals; no allocation allowed) ----------------
__device__ float g_q[Bz*Nz*Cz];
__device__ float g_k[Bz*Nz*Cz];
__device__ float g_v[Bz*Nz*Cz];
__device__ int   g_idx[Bz*Nz*Kz];
// folded params (weights in c-quad float4 layout: w[c4*256 + o*4 + j] = W[o][4c4+j])
__device__ float g_pe_w1f[Cz*3];
__device__ float g_b_pef[Cz];
__device__ float g_pe_w2q[Cz*Cz];
__device__ float g_pe_b2c[Cz];
__device__ float g_s0[Cz], g_b0[Cz];
__device__ float g_at_w1q[Cz*Cz];    // rows scaled by s1[o]
__device__ float g_bb1[Cz];
__device__ float g_at_w2q[Cz*Cz];
__device__ float g_at_b2c[Cz];

// packed f32x2 fma (FFMA2; only reachable via PTX)
__device__ __forceinline__ float2 fma2(float2 a, float2 b, float2 c) {
    unsigned long long A = *(unsigned long long*)&a;
    unsigned long long B = *(unsigned long long*)&b;
    unsigned long long C = *(unsigned long long*)&c;
    unsigned long long D;
    asm("fma.rn.f32x2 %0, %1, %2, %3;" : "=l"(D) : "l"(A), "l"(B), "l"(C));
    return *(float2*)&D;
}

// ---------------- kernel 1: qkv + fold + p-copy ----------------
// qkv branch is the R11-measured 38.0us config: 256 threads, unroll 4, 252 regs, NO spills.
__global__ __launch_bounds__(256)
void qkv_fold_kernel(
    const float* __restrict__ p, float* __restrict__ out,
    const float* __restrict__ x,
    const float* __restrict__ Wq, const float* __restrict__ bq,
    const float* __restrict__ Wk, const float* __restrict__ bk,
    const float* __restrict__ Wv, const float* __restrict__ bv,
    const float* __restrict__ pe_w1,
    const float* __restrict__ pbg, const float* __restrict__ pbb,
    const float* __restrict__ pbm, const float* __restrict__ pbv,
    const float* __restrict__ pe_w2, const float* __restrict__ pe_b2,
    const float* __restrict__ a0g, const float* __restrict__ a0b,
    const float* __restrict__ a0m, const float* __restrict__ a0v,
    const float* __restrict__ at_w1,
    const float* __restrict__ a1g, const float* __restrict__ a1b,
    const float* __restrict__ a1m, const float* __restrict__ a1v,
    const float* __restrict__ at_w2, const float* __restrict__ at_b2)
{
    extern __shared__ float dyn[];
    int t = threadIdx.x;

    if (blockIdx.x > QKV_BLOCKS) {
        // ---- p -> out copy (output tuple = (p, y); p first) ----
        int cb = blockIdx.x - (QKV_BLOCKS + 1);
        int base = cb * 256 * 16;
        const float4* src = (const float4*)p;
        float4* dst = (float4*)out;
        #pragma unroll
        for (int i = 0; i < 4; i++) {
            int idx = (base >> 2) + t + i * 256;   // float4 index
            if (idx < (Bz*Nz*3) / 4) dst[idx] = src[idx];
        }
        return;
    }

    if (blockIdx.x == QKV_BLOCKS) {
        // ---- fold block ----
        __shared__ float s1sh[Cz];
        if (t < Cz) {
            float spe = pbg[t] * rsqrtf(pbv[t] + EPSf);
            g_b_pef[t] = pbb[t] - pbm[t] * spe;
            #pragma unroll
            for (int j = 0; j < 3; j++) g_pe_w1f[t*3+j] = pe_w1[t*3+j] * spe;
            g_pe_b2c[t] = pe_b2[t];
            float s0 = a0g[t] * rsqrtf(a0v[t] + EPSf);
            g_s0[t] = s0;
            g_b0[t] = a0b[t] - a0m[t] * s0;
            float s1 = a1g[t] * rsqrtf(a1v[t] + EPSf);
            s1sh[t] = s1;
            g_bb1[t] = a1b[t] - a1m[t] * s1;
            g_at_b2c[t] = at_b2[t];
        }
        __syncthreads();
        for (int i = t; i < 64*16; i += blockDim.x) {
            int o = i & 63, c4 = i >> 6;
            float s1v = s1sh[o];
            #pragma unroll
            for (int j = 0; j < 4; j++) {
                int d = c4*256 + o*4 + j;
                int s = o*Cz + 4*c4 + j;
                g_pe_w2q[d] = pe_w2[s];
                g_at_w1q[d] = at_w1[s] * s1v;
                g_at_w2q[d] = at_w2[s];
            }
        }
        return;
    }

    // ---- qkv blocks: x transposed [j][c] (68-pad), weights row-major [o][c] (68-pad) ----
    float* xs = dyn;             // [64 j][68]
    float* wq = xs + 64*68;      // [64 o][68]
    float* wk = wq + 64*68;
    float* wv = wk + 64*68;

    int b  = blockIdx.x >> 6;
    int n0 = (blockIdx.x & 63) * 64;

    for (int i = t; i < 4096; i += 256) {
        int o = i >> 6, c = i & 63;
        wq[o*68 + c] = Wq[i]; wk[o*68 + c] = Wk[i]; wv[o*68 + c] = Wv[i];
    }
    for (int i = t; i < 4096; i += 256) {
        int c = i >> 6, j = i & 63;
        xs[j*68 + c] = x[(b*Cz + c)*Nz + n0 + j];   // coalesced gmem read
    }
    __syncthreads();

    int o  = t & 63;
    int jg = t >> 6;                 // 0..3, 16 j each
    float bqo = bq[o], bko = bk[o], bvo = bv[o];
    const float4* wq4 = (const float4*)(wq + o*68);
    const float4* wk4 = (const float4*)(wk + o*68);
    const float4* wv4 = (const float4*)(wv + o*68);

    #pragma unroll 4
    for (int jj = 0; jj < 16; jj++) {
        int j = jg*16 + jj;
        const float4* xs4 = (const float4*)(xs + j*68);
        float2 aq01 = make_float2(0.f,0.f), aq23 = make_float2(0.f,0.f);
        float2 ak01 = make_float2(0.f,0.f), ak23 = make_float2(0.f,0.f);
        float2 av01 = make_float2(0.f,0.f), av23 = make_float2(0.f,0.f);
        #pragma unroll
        for (int c4 = 0; c4 < 16; c4++) {
            float4 xv = xs4[c4];
            float2 x01 = make_float2(xv.x, xv.y), x23 = make_float2(xv.z, xv.w);
            float4 w;
            w = wq4[c4];
            aq01 = fma2(make_float2(w.x,w.y), x01, aq01);
            aq23 = fma2(make_float2(w.z,w.w), x23, aq23);
            w = wk4[c4];
            ak01 = fma2(make_float2(w.x,w.y), x01, ak01);
            ak23 = fma2(make_float2(w.z,w.w), x23, ak23);
            w = wv4[c4];
            av01 = fma2(make_float2(w.x,w.y), x01, av01);
            av23 = fma2(make_float2(w.z,w.w), x23, av23);
        }
        int base = ((b*Nz) + n0 + j)*Cz + o;
        g_q[base] = ((aq01.x + aq01.y) + (aq23.x + aq23.y)) + bqo;
        g_k[base] = ((ak01.x + ak01.y) + (ak23.x + ak23.y)) + bko;
        g_v[base] = ((av01.x + av01.y) + (av23.x + av23.y)) + bvo;
    }
}

// ---------------- kernel 2: KNN — 2 candidates/lane, INF-validity, per-hit recheck ----------------
// R11-measured config: grid = 1024, 512 threads (16 warps = 16 queries), smem 64KB.
__global__ __launch_bounds__(KWARPS*32)
void knn_kernel(const float* __restrict__ p)
{
    extern __shared__ float dyn[];
    float4* p4 = (float4*)dyn;   // [4096] (x,y,z,ssq | +INF if invalid)

    int t = threadIdx.x, lane = t & 31, warp = t >> 5;
    int blksPerB = Nz / KWARPS;           // 256
    int b = blockIdx.x / blksPerB;
    int n = (blockIdx.x - b*blksPerB) * KWARPS + warp;

    const float INF = __int_as_float(0x7f800000);
    const float* pb3 = p + b*Nz*3;
    for (int m = t; m < Nz; m += KWARPS*32) {
        float x0 = __ldg(pb3 + 3*m), y0 = __ldg(pb3 + 3*m + 1), z0 = __ldg(pb3 + 3*m + 2);
        // ssq rounded exactly as the reference: (x*x + y*y) + z*z; +INF marks invalid point
        float ss = __fadd_rn(__fadd_rn(__fmul_rn(x0,x0), __fmul_rn(y0,y0)), __fmul_rn(z0,z0));
        bool invalid = (x0 == 0.f) && (y0 == 0.f) && (z0 == 0.f);
        p4[m] = make_float4(x0, y0, z0, invalid ? INF : ss);
    }
    __syncthreads();

    float4 q4 = p4[n];
    float qx = q4.x, qy = q4.y, qz = q4.z;
    float qsq = __fadd_rn(__fadd_rn(__fmul_rn(qx,qx), __fmul_rn(qy,qy)), __fmul_rn(qz,qz));

    // warp-distributed sorted list (ascending by (d2, idx)); lanes 0..15 = top-16
    float lv = FLT_BIG;
    int   li = 0x7fffffff;
    float kthv = FLT_BIG;
    int   kthi = 0x7fffffff;

    // uniform sorted-shift insert of (v,i), with per-hit recheck + kth refresh
    auto insert = [&](unsigned mask, float d2, int m) {
        while (mask) {
            int src = __ffs(mask) - 1;
            mask &= mask - 1;
            float v = __shfl_sync(FULLMASK, d2, src);
            int   i = __shfl_sync(FULLMASK, m, src);
            if ((v < kthv) || (v == kthv && i < kthi)) {   // skip hits made obsolete this batch
                float upv = __shfl_up_sync(FULLMASK, lv, 1);
                int   upi = __shfl_up_sync(FULLMASK, li, 1);
                bool gt  = (lv > v)  || (lv == v  && li > i);
                bool gtu = (lane > 0) && ((upv > v) || (upv == v && upi > i));
                if (gt) {
                    lv = gtu ? upv : v;
                    li = gtu ? upi : i;
                }
                kthv = __shfl_sync(FULLMASK, lv, 15);
                kthi = __shfl_sync(FULLMASK, li, 15);
            }
        }
    };

    for (int base = 0; base < Nz; base += 64) {
        int m0 = base + lane;
        int m1 = m0 + 32;
        float4 ca = p4[m0];
        float4 cb = p4[m1];
        // d2 = (sq_n + sq_m) - 2*dot, un-contracted fp to match reference ranking
        float dota = __fadd_rn(__fadd_rn(__fmul_rn(ca.x,qx), __fmul_rn(ca.y,qy)), __fmul_rn(ca.z,qz));
        float d2a  = __fadd_rn(__fadd_rn(qsq, ca.w), -__fmul_rn(2.0f, dota));
        float dotb = __fadd_rn(__fadd_rn(__fmul_rn(cb.x,qx), __fmul_rn(cb.y,qy)), __fmul_rn(cb.z,qz));
        float d2b  = __fadd_rn(__fadd_rn(qsq, cb.w), -__fmul_rn(2.0f, dotb));

        bool hit0 = (d2a < kthv) || (d2a == kthv && m0 < kthi);
        bool hit1 = (d2b < kthv) || (d2b == kthv && m1 < kthi);
        unsigned mask0 = __ballot_sync(FULLMASK, hit0);
        unsigned mask1 = __ballot_sync(FULLMASK, hit1);
        if (mask0 | mask1) {
            insert(mask0, d2a, m0);
            insert(mask1, d2b, m1);
        }
    }

    if (lane < Kz) g_idx[(b*Nz + n)*Kz + lane] = li;
}

// ---------------- warp-solo gemvs (single pass, acc[16][2] — ~168 regs, NO spills) ----------------
__device__ __forceinline__ void gemv_core(
    const float* __restrict__ Wq, const float* __restrict__ inb,
    int lane, float2 acc[16][2])
{
    const float4* W4 = (const float4*)Wq;
    #pragma unroll
    for (int r = 0; r < 16; r++) { acc[r][0] = make_float2(0.f,0.f); acc[r][1] = make_float2(0.f,0.f); }
    #pragma unroll
    for (int c4 = 0; c4 < 16; c4++) {
        float4 wA = W4[c4*64 + lane];
        float4 wB = W4[c4*64 + lane + 32];
        float2 wA01 = make_float2(wA.x, wA.y), wA23 = make_float2(wA.z, wA.w);
        float2 wB01 = make_float2(wB.x, wB.y), wB23 = make_float2(wB.z, wB.w);
        #pragma unroll
        for (int r = 0; r < 16; r++) {
            float4 xv = *(const float4*)&inb[r*64 + 4*c4];    // broadcast
            float2 x01 = make_float2(xv.x, xv.y), x23 = make_float2(xv.z, xv.w);
            acc[r][0] = fma2(wA01, x01, acc[r][0]);
            acc[r][0] = fma2(wA23, x23, acc[r][0]);
            acc[r][1] = fma2(wB01, x01, acc[r][1]);
            acc[r][1] = fma2(wB23, x23, acc[r][1]);
        }
    }
}

__device__ __forceinline__ void gemv_regs(
    const float* __restrict__ Wq, const float* __restrict__ inb,
    const float* __restrict__ bias, int lane, float o0[16], float o1[16])
{
    float2 acc[16][2];
    gemv_core(Wq, inb, lane, acc);
    float ba = bias[lane], bb = bias[lane + 32];
    #pragma unroll
    for (int r = 0; r < 16; r++) {
        o0[r] = (acc[r][0].x + acc[r][0].y) + ba;
        o1[r] = (acc[r][1].x + acc[r][1].y) + bb;
    }
}

__device__ __forceinline__ void gemv_smem_relu(
    const float* __restrict__ Wq, const float* __restrict__ inb,
    float* __restrict__ outb, const float* __restrict__ bias, int lane)
{
    float2 acc[16][2];
    gemv_core(Wq, inb, lane, acc);
    float ba = bias[lane], bb = bias[lane + 32];
    #pragma unroll
    for (int r = 0; r < 16; r++) {
        outb[r*64 + lane]      = fmaxf((acc[r][0].x + acc[r][0].y) + ba, 0.f);
        outb[r*64 + lane + 32] = fmaxf((acc[r][1].x + acc[r][1].y) + bb, 0.f);
    }
}

// ---------------- kernel 3: warp-per-point fused MLP pipeline, zero barriers ----------------
// R11-measured config: 152 persistent blocks, 384 threads (12 warps), nr/a4 in registers,
// 168 regs (full RF), smem ~150KB. Measured local optimum — do not perturb.
__global__ __launch_bounds__(NWARP*32, 1)
void main_kernel(const float* __restrict__ p, float* __restrict__ out)
{
    extern __shared__ float dyn[];
    float* w2t = dyn;              // pe_w2 c-quad       4096
    float* w1a = w2t + 4096;       // at_w1 c-quad       4096
    float* w2a = w1a + 4096;       // at_w2 c-quad       4096
    float* pe1 = w2a + 4096;       // 192
    float* bpe = pe1 + 192;        // 64
    float* pb2 = bpe + 64;
    float* s0  = pb2 + 64;
    float* b0  = s0  + 64;
    float* bb1 = b0  + 64;
    float* ab2 = bb1 + 64;
    float* bufs = ab2 + 64;        // [NWARP][2][1024]

    int t = threadIdx.x, lane = t & 31, warp = t >> 5;

    for (int i = t; i < 4096; i += NWARP*32) {
        w2t[i] = g_pe_w2q[i];
        w1a[i] = g_at_w1q[i];
        w2a[i] = g_at_w2q[i];
    }
    if (t < 192) pe1[t] = g_pe_w1f[t];
    if (t >= 192 && t < 256) {
        int c = t - 192;
        bpe[c] = g_b_pef[c]; pb2[c] = g_pe_b2c[c];
        s0[c]  = g_s0[c];    b0[c]  = g_b0[c];
        bb1[c] = g_bb1[c];   ab2[c] = g_at_b2c[c];
    }
    __syncthreads();

    int c0 = lane, c1 = lane + 32;
    float pa0 = pe1[c0*3], pa1 = pe1[c0*3+1], pa2 = pe1[c0*3+2];
    float pq0 = pe1[c1*3], pq1 = pe1[c1*3+1], pq2 = pe1[c1*3+2];
    float bpa = bpe[c0], bpb = bpe[c1];
    float s0a = s0[c0],  s0b = s0[c1];
    float b0a = b0[c0],  b0b = b0[c1];

    float* B0 = bufs + warp*2048;        // h / a1
    float* B2 = B0 + 1024;               // a3

    const int stride = MAIN_GRID * NWARP;
    for (int g = blockIdx.x * NWARP + warp; g < Bz*Nz; g += stride) {
        int b = g >> 12, n = g & 4095;
        const float* pb3 = p + b*Nz*3;
        int bN64 = b*Nz*Cz;

        int idv[Kz];
        #pragma unroll
        for (int k = 0; k < Kz; k++) idv[k] = __ldg(g_idx + g*Kz + k);

        float psx = __ldg(p + g*3), psy = __ldg(p + g*3 + 1), psz = __ldg(p + g*3 + 2);

        // h[k][c] = relu(pe_w1f @ (p - pn) + b_pef)
        #pragma unroll
        for (int k = 0; k < Kz; k++) {
            int id = idv[k];
            float rx = psx - __ldg(pb3 + id*3);
            float ry = psy - __ldg(pb3 + id*3 + 1);
            float rz = psz - __ldg(pb3 + id*3 + 2);
            float h0 = fmaf(pa0, rx, fmaf(pa1, ry, fmaf(pa2, rz, bpa)));
            float h1 = fmaf(pq0, rx, fmaf(pq1, ry, fmaf(pq2, rz, bpb)));
            B0[k*64 + c0] = fmaxf(h0, 0.f);
            B0[k*64 + c1] = fmaxf(h1, 0.f);
        }
        __syncwarp();

        // n_r in registers (lane owns c0, c1 per k)
        float nr0[Kz], nr1[Kz];
        gemv_regs(w2t, B0, pb2, lane, nr0, nr1);
        __syncwarp();

        // a1[k][c] = relu((q - n_k + n_r)*s0 + b0) -> B0
        float qa = __ldg(g_q + g*Cz + c0), qb = __ldg(g_q + g*Cz + c1);
        #pragma unroll
        for (int k = 0; k < Kz; k++) {
            int base = bN64 + idv[k]*Cz;
            float nk0 = __ldg(g_k + base + c0);
            float nk1 = __ldg(g_k + base + c1);
            float a0x = fmaf(qa - nk0 + nr0[k], s0a, b0a);
            float a1x = fmaf(qb - nk1 + nr1[k], s0b, b0b);
            B0[k*64 + c0] = fmaxf(a0x, 0.f);
            B0[k*64 + c1] = fmaxf(a1x, 0.f);
        }
        __syncwarp();

        // a3[k][o] = relu(at_w1' @ a1 + bb1) -> B2
        gemv_smem_relu(w1a, B0, B2, bb1, lane);
        __syncwarp();

        // a4 in registers
        float a40[Kz], a41[Kz];
        gemv_regs(w2a, B2, ab2, lane, a40, a41);

        // softmax over k + aggregate, entirely in registers (mask all-true)
        float* outp = out + Bz*Nz*3 + (b*Cz)*Nz + n;
        {
            float mx0 = -FLT_BIG, mx1 = -FLT_BIG;
            #pragma unroll
            for (int k = 0; k < Kz; k++) { mx0 = fmaxf(mx0, a40[k]); mx1 = fmaxf(mx1, a41[k]); }
            float sA = 0.f, sB = 0.f;
            #pragma unroll
            for (int k = 0; k < Kz; k++) {
                a40[k] = __expf(a40[k] - mx0); sA += a40[k];
                a41[k] = __expf(a41[k] - mx1); sB += a41[k];
            }
            float invA = 1.f / sA, invB = 1.f / sB;
            float y0 = 0.f, y1 = 0.f;
            #pragma unroll
            for (int k = 0; k < Kz; k++) {
                int base = bN64 + idv[k]*Cz;
                float v0 = __ldg(g_v + base + c0);
                float v1 = __ldg(g_v + base + c1);
                y0 = fmaf(a40[k]*invA, v0 + nr0[k], y0);
                y1 = fmaf(a41[k]*invB, v1 + nr1[k], y1);
            }
            outp[c0*Nz] = y0;
            outp[c1*Nz] = y1;
        }
        __syncwarp();
    }
}

// ---------------- launch ----------------
extern "C" void kernel_launch(void* const* d_in, const int* in_sizes, int n_in,
                              void* d_out, int out_size)
{
    const float* p     = (const float*)d_in[0];
    const float* x     = (const float*)d_in[1];
    // d_in[2] = mask, all-true by construction -> unused
    const float* Wq    = (const float*)d_in[3];
    const float* bq    = (const float*)d_in[4];
    const float* Wk    = (const float*)d_in[5];
    const float* bk    = (const float*)d_in[6];
    const float* Wv    = (const float*)d_in[7];
    const float* bv    = (const float*)d_in[8];
    const float* pe_w1 = (const float*)d_in[9];
    const float* pbg   = (const float*)d_in[10];
    const float* pbb   = (const float*)d_in[11];
    const float* pbm   = (const float*)d_in[12];
    const float* pbv   = (const float*)d_in[13];
    const float* pe_w2 = (const float*)d_in[14];
    const float* pe_b2 = (const float*)d_in[15];
    const float* a0g   = (const float*)d_in[16];
    const float* a0b   = (const float*)d_in[17];
    const float* a0m   = (const float*)d_in[18];
    const float* a0v   = (const float*)d_in[19];
    const float* at_w1 = (const float*)d_in[20];
    const float* a1g   = (const float*)d_in[21];
    const float* a1b   = (const float*)d_in[22];
    const float* a1m   = (const float*)d_in[23];
    const float* a1v   = (const float*)d_in[24];
    const float* at_w2 = (const float*)d_in[25];
    const float* at_b2 = (const float*)d_in[26];

    float* out = (float*)d_out;

    const int QKV_SMEM  = QKV_FLOATS * (int)sizeof(float);            // ~69.6KB
    const int KNN_SMEM  = Nz * 4 * (int)sizeof(float);                // 64KB
    const int MAIN_SMEM = MAIN_FLOATS * (int)sizeof(float);           // ~150KB

    cudaFuncSetAttribute(qkv_fold_kernel, cudaFuncAttributeMaxDynamicSharedMemorySize, QKV_SMEM);
    cudaFuncSetAttribute(knn_kernel,      cudaFuncAttributeMaxDynamicSharedMemorySize, KNN_SMEM);
    cudaFuncSetAttribute(main_kernel,     cudaFuncAttributeMaxDynamicSharedMemorySize, MAIN_SMEM);

    qkv_fold_kernel<<<K1_GRID, 256, QKV_SMEM>>>(
        p, out, x, Wq, bq, Wk, bk, Wv, bv,
        pe_w1, pbg, pbb, pbm, pbv, pe_w2, pe_b2,
        a0g, a0b, a0m, a0v, at_w1,
        a1g, a1b, a1m, a1v, at_w2, at_b2);

    knn_kernel<<<Bz*(Nz/KWARPS), KWARPS*32, KNN_SMEM>>>(p);

    main_kernel<<<MAIN_GRID, NWARP*32, MAIN_SMEM>>>(p, out);
}

// round 16
// speedup vs baseline: 1.3585x; 1.0018x over previous
#include <cuda_runtime.h>
#include <math.h>

#define Bz 4
#define Nz 4096
#define Cz 64
#define Kz 16
#define EPSf 1e-5f
#define FLT_BIG 3.402823466e38f
#define FULLMASK 0xffffffffu

#define NWARP 12
#define MAIN_GRID 152
#define KWARPS 16          // queries per knn block

#define W_FLOATS 12864     // 3*4096 weights + 192 pe1 + 6*64 biases
#define MAIN_FLOATS (W_FLOATS + NWARP*2048)   // 37440 -> 149.76 KB

// qkv smem: xs [64][68] + 3 weight mats [64][68] = 4*4352 = 17408 floats (69.6KB)
#define QKV_FLOATS (4*64*68)

// kernel-1 grid: [0,256) qkv, 256 fold, [257,269) p->out copy, [269,285) p4 build
#define QKV_BLOCKS (Bz*(Nz/64))     // 256
#define COPY_BLOCKS 12              // 49152 floats / (256 thr * 16) = 12
#define P4_BLOCKS 16                // 16384 points / (256 thr * 4) = 16
#define K1_GRID (QKV_BLOCKS + 1 + COPY_BLOCKS + P4_BLOCKS)

// ---------------- scratch (device globals; no allocation allowed) ----------------
__device__ float g_q[Bz*Nz*Cz];
__device__ float g_k[Bz*Nz*Cz];
__device__ float g_v[Bz*Nz*Cz];
__device__ int   g_idx[Bz*Nz*Kz];
__device__ float4 g_p4[Bz*Nz];       // (x,y,z, ssq | +INF if invalid), built in kernel 1
// folded params (weights in c-quad float4 layout: w[c4*256 + o*4 + j] = W[o][4c4+j])
__device__ float g_pe_w1f[Cz*3];
__device__ float g_b_pef[Cz];
__device__ float g_pe_w2q[Cz*Cz];
__device__ float g_pe_b2c[Cz];
__device__ float g_s0[Cz], g_b0[Cz];
__device__ float g_at_w1q[Cz*Cz];    // rows scaled by s1[o]
__device__ float g_bb1[Cz];
__device__ float g_at_w2q[Cz*Cz];
__device__ float g_at_b2c[Cz];

// packed f32x2 fma (FFMA2; only reachable via PTX)
__device__ __forceinline__ float2 fma2(float2 a, float2 b, float2 c) {
    unsigned long long A = *(unsigned long long*)&a;
    unsigned long long B = *(unsigned long long*)&b;
    unsigned long long C = *(unsigned long long*)&c;
    unsigned long long D;
    asm("fma.rn.f32x2 %0, %1, %2, %3;" : "=l"(D) : "l"(A), "l"(B), "l"(C));
    return *(float2*)&D;
}

// ---------------- kernel 1: qkv + fold + p-copy + p4 build ----------------
// qkv branch is the R11-measured 38.0us config: 256 threads, unroll 4, 252 regs, NO spills.
__global__ __launch_bounds__(256)
void qkv_fold_kernel(
    const float* __restrict__ p, float* __restrict__ out,
    const float* __restrict__ x,
    const float* __restrict__ Wq, const float* __restrict__ bq,
    const float* __restrict__ Wk, const float* __restrict__ bk,
    const float* __restrict__ Wv, const float* __restrict__ bv,
    const float* __restrict__ pe_w1,
    const float* __restrict__ pbg, const float* __restrict__ pbb,
    const float* __restrict__ pbm, const float* __restrict__ pbv,
    const float* __restrict__ pe_w2, const float* __restrict__ pe_b2,
    const float* __restrict__ a0g, const float* __restrict__ a0b,
    const float* __restrict__ a0m, const float* __restrict__ a0v,
    const float* __restrict__ at_w1,
    const float* __restrict__ a1g, const float* __restrict__ a1b,
    const float* __restrict__ a1m, const float* __restrict__ a1v,
    const float* __restrict__ at_w2, const float* __restrict__ at_b2)
{
    extern __shared__ float dyn[];
    int t = threadIdx.x;

    if (blockIdx.x >= QKV_BLOCKS + 1 + COPY_BLOCKS) {
        // ---- p4 build: (x,y,z, ssq|INF) per point, reference-rounded ssq ----
        const float INF = __int_as_float(0x7f800000);
        int pb = blockIdx.x - (QKV_BLOCKS + 1 + COPY_BLOCKS);
        int base = pb * 1024;
        #pragma unroll
        for (int i = 0; i < 4; i++) {
            int m = base + i*256 + t;
            float x0 = p[3*m], y0 = p[3*m + 1], z0 = p[3*m + 2];
            float ss = __fadd_rn(__fadd_rn(__fmul_rn(x0,x0), __fmul_rn(y0,y0)), __fmul_rn(z0,z0));
            bool invalid = (x0 == 0.f) && (y0 == 0.f) && (z0 == 0.f);
            g_p4[m] = make_float4(x0, y0, z0, invalid ? INF : ss);
        }
        return;
    }

    if (blockIdx.x > QKV_BLOCKS) {
        // ---- p -> out copy (output tuple = (p, y); p first) ----
        int cb = blockIdx.x - (QKV_BLOCKS + 1);
        int base = cb * 256 * 16;
        const float4* src = (const float4*)p;
        float4* dst = (float4*)out;
        #pragma unroll
        for (int i = 0; i < 4; i++) {
            int idx = (base >> 2) + t + i * 256;   // float4 index
            if (idx < (Bz*Nz*3) / 4) dst[idx] = src[idx];
        }
        return;
    }

    if (blockIdx.x == QKV_BLOCKS) {
        // ---- fold block ----
        __shared__ float s1sh[Cz];
        if (t < Cz) {
            float spe = pbg[t] * rsqrtf(pbv[t] + EPSf);
            g_b_pef[t] = pbb[t] - pbm[t] * spe;
            #pragma unroll
            for (int j = 0; j < 3; j++) g_pe_w1f[t*3+j] = pe_w1[t*3+j] * spe;
            g_pe_b2c[t] = pe_b2[t];
            float s0 = a0g[t] * rsqrtf(a0v[t] + EPSf);
            g_s0[t] = s0;
            g_b0[t] = a0b[t] - a0m[t] * s0;
            float s1 = a1g[t] * rsqrtf(a1v[t] + EPSf);
            s1sh[t] = s1;
            g_bb1[t] = a1b[t] - a1m[t] * s1;
            g_at_b2c[t] = at_b2[t];
        }
        __syncthreads();
        for (int i = t; i < 64*16; i += blockDim.x) {
            int o = i & 63, c4 = i >> 6;
            float s1v = s1sh[o];
            #pragma unroll
            for (int j = 0; j < 4; j++) {
                int d = c4*256 + o*4 + j;
                int s = o*Cz + 4*c4 + j;
                g_pe_w2q[d] = pe_w2[s];
                g_at_w1q[d] = at_w1[s] * s1v;
                g_at_w2q[d] = at_w2[s];
            }
        }
        return;
    }

    // ---- qkv blocks: x transposed [j][c] (68-pad), weights row-major [o][c] (68-pad) ----
    float* xs = dyn;             // [64 j][68]
    float* wq = xs + 64*68;      // [64 o][68]
    float* wk = wq + 64*68;
    float* wv = wk + 64*68;

    int b  = blockIdx.x >> 6;
    int n0 = (blockIdx.x & 63) * 64;

    for (int i = t; i < 4096; i += 256) {
        int o = i >> 6, c = i & 63;
        wq[o*68 + c] = Wq[i]; wk[o*68 + c] = Wk[i]; wv[o*68 + c] = Wv[i];
    }
    for (int i = t; i < 4096; i += 256) {
        int c = i >> 6, j = i & 63;
        xs[j*68 + c] = x[(b*Cz + c)*Nz + n0 + j];   // coalesced gmem read
    }
    __syncthreads();

    int o  = t & 63;
    int jg = t >> 6;                 // 0..3, 16 j each
    float bqo = bq[o], bko = bk[o], bvo = bv[o];
    const float4* wq4 = (const float4*)(wq + o*68);
    const float4* wk4 = (const float4*)(wk + o*68);
    const float4* wv4 = (const float4*)(wv + o*68);

    #pragma unroll 4
    for (int jj = 0; jj < 16; jj++) {
        int j = jg*16 + jj;
        const float4* xs4 = (const float4*)(xs + j*68);
        float2 aq01 = make_float2(0.f,0.f), aq23 = make_float2(0.f,0.f);
        float2 ak01 = make_float2(0.f,0.f), ak23 = make_float2(0.f,0.f);
        float2 av01 = make_float2(0.f,0.f), av23 = make_float2(0.f,0.f);
        #pragma unroll
        for (int c4 = 0; c4 < 16; c4++) {
            float4 xv = xs4[c4];
            float2 x01 = make_float2(xv.x, xv.y), x23 = make_float2(xv.z, xv.w);
            float4 w;
            w = wq4[c4];
            aq01 = fma2(make_float2(w.x,w.y), x01, aq01);
            aq23 = fma2(make_float2(w.z,w.w), x23, aq23);
            w = wk4[c4];
            ak01 = fma2(make_float2(w.x,w.y), x01, ak01);
            ak23 = fma2(make_float2(w.z,w.w), x23, ak23);
            w = wv4[c4];
            av01 = fma2(make_float2(w.x,w.y), x01, av01);
            av23 = fma2(make_float2(w.z,w.w), x23, av23);
        }
        int base = ((b*Nz) + n0 + j)*Cz + o;
        g_q[base] = ((aq01.x + aq01.y) + (aq23.x + aq23.y)) + bqo;
        g_k[base] = ((ak01.x + ak01.y) + (ak23.x + ak23.y)) + bko;
        g_v[base] = ((av01.x + av01.y) + (av23.x + av23.y)) + bvo;
    }
}

// ---------------- kernel 2: KNN — zero smem, L1-resident g_p4 scan via __ldg ----------------
// No staging, no barriers; 4 blocks/SM (thread-limited) = 64 warps/SM.
// Scan/insert semantics identical to the R11-measured optimum.
__global__ __launch_bounds__(KWARPS*32)
void knn_kernel()
{
    int t = threadIdx.x, lane = t & 31, warp = t >> 5;
    int blksPerB = Nz / KWARPS;           // 256
    int b = blockIdx.x / blksPerB;
    int n = (blockIdx.x - b*blksPerB) * KWARPS + warp;

    const float4* p4 = g_p4 + b*Nz;

    float4 q4 = __ldg(p4 + n);
    float qx = q4.x, qy = q4.y, qz = q4.z;
    // recompute qsq (the slot may carry +INF if the query point is invalid)
    float qsq = __fadd_rn(__fadd_rn(__fmul_rn(qx,qx), __fmul_rn(qy,qy)), __fmul_rn(qz,qz));

    // warp-distributed sorted list (ascending by (d2, idx)); lanes 0..15 = top-16
    float lv = FLT_BIG;
    int   li = 0x7fffffff;
    float kthv = FLT_BIG;
    int   kthi = 0x7fffffff;

    // uniform sorted-shift insert of (v,i), with per-hit recheck + kth refresh
    auto insert = [&](unsigned mask, float d2, int m) {
        while (mask) {
            int src = __ffs(mask) - 1;
            mask &= mask - 1;
            float v = __shfl_sync(FULLMASK, d2, src);
            int   i = __shfl_sync(FULLMASK, m, src);
            if ((v < kthv) || (v == kthv && i < kthi)) {   // skip hits made obsolete this batch
                float upv = __shfl_up_sync(FULLMASK, lv, 1);
                int   upi = __shfl_up_sync(FULLMASK, li, 1);
                bool gt  = (lv > v)  || (lv == v  && li > i);
                bool gtu = (lane > 0) && ((upv > v) || (upv == v && upi > i));
                if (gt) {
                    lv = gtu ? upv : v;
                    li = gtu ? upi : i;
                }
                kthv = __shfl_sync(FULLMASK, lv, 15);
                kthi = __shfl_sync(FULLMASK, li, 15);
            }
        }
    };

    for (int base = 0; base < Nz; base += 64) {
        int m0 = base + lane;
        int m1 = m0 + 32;
        float4 ca = __ldg(p4 + m0);
        float4 cb = __ldg(p4 + m1);
        // d2 = (sq_n + sq_m) - 2*dot, un-contracted fp to match reference ranking
        float dota = __fadd_rn(__fadd_rn(__fmul_rn(ca.x,qx), __fmul_rn(ca.y,qy)), __fmul_rn(ca.z,qz));
        float d2a  = __fadd_rn(__fadd_rn(qsq, ca.w), -__fmul_rn(2.0f, dota));
        float dotb = __fadd_rn(__fadd_rn(__fmul_rn(cb.x,qx), __fmul_rn(cb.y,qy)), __fmul_rn(cb.z,qz));
        float d2b  = __fadd_rn(__fadd_rn(qsq, cb.w), -__fmul_rn(2.0f, dotb));

        bool hit0 = (d2a < kthv) || (d2a == kthv && m0 < kthi);
        bool hit1 = (d2b < kthv) || (d2b == kthv && m1 < kthi);
        unsigned mask0 = __ballot_sync(FULLMASK, hit0);
        unsigned mask1 = __ballot_sync(FULLMASK, hit1);
        if (mask0 | mask1) {
            insert(mask0, d2a, m0);
            insert(mask1, d2b, m1);
        }
    }

    if (lane < Kz) g_idx[(b*Nz + n)*Kz + lane] = li;
}

// ---------------- warp-solo gemvs (single pass, acc[16][2] — ~168 regs, NO spills) ----------------
__device__ __forceinline__ void gemv_core(
    const float* __restrict__ Wq, const float* __restrict__ inb,
    int lane, float2 acc[16][2])
{
    const float4* W4 = (const float4*)Wq;
    #pragma unroll
    for (int r = 0; r < 16; r++) { acc[r][0] = make_float2(0.f,0.f); acc[r][1] = make_float2(0.f,0.f); }
    #pragma unroll
    for (int c4 = 0; c4 < 16; c4++) {
        float4 wA = W4[c4*64 + lane];
        float4 wB = W4[c4*64 + lane + 32];
        float2 wA01 = make_float2(wA.x, wA.y), wA23 = make_float2(wA.z, wA.w);
        float2 wB01 = make_float2(wB.x, wB.y), wB23 = make_float2(wB.z, wB.w);
        #pragma unroll
        for (int r = 0; r < 16; r++) {
            float4 xv = *(const float4*)&inb[r*64 + 4*c4];    // broadcast
            float2 x01 = make_float2(xv.x, xv.y), x23 = make_float2(xv.z, xv.w);
            acc[r][0] = fma2(wA01, x01, acc[r][0]);
            acc[r][0] = fma2(wA23, x23, acc[r][0]);
            acc[r][1] = fma2(wB01, x01, acc[r][1]);
            acc[r][1] = fma2(wB23, x23, acc[r][1]);
        }
    }
}

__device__ __forceinline__ void gemv_regs(
    const float* __restrict__ Wq, const float* __restrict__ inb,
    const float* __restrict__ bias, int lane, float o0[16], float o1[16])
{
    float2 acc[16][2];
    gemv_core(Wq, inb, lane, acc);
    float ba = bias[lane], bb = bias[lane + 32];
    #pragma unroll
    for (int r = 0; r < 16; r++) {
        o0[r] = (acc[r][0].x + acc[r][0].y) + ba;
        o1[r] = (acc[r][1].x + acc[r][1].y) + bb;
    }
}

__device__ __forceinline__ void gemv_smem_relu(
    const float* __restrict__ Wq, const float* __restrict__ inb,
    float* __restrict__ outb, const float* __restrict__ bias, int lane)
{
    float2 acc[16][2];
    gemv_core(Wq, inb, lane, acc);
    float ba = bias[lane], bb = bias[lane + 32];
    #pragma unroll
    for (int r = 0; r < 16; r++) {
        outb[r*64 + lane]      = fmaxf((acc[r][0].x + acc[r][0].y) + ba, 0.f);
        outb[r*64 + lane + 32] = fmaxf((acc[r][1].x + acc[r][1].y) + bb, 0.f);
    }
}

// ---------------- kernel 3: warp-per-point fused MLP pipeline, zero barriers ----------------
// R11-measured config: 152 persistent blocks, 384 threads (12 warps), nr/a4 in registers,
// 168 regs (full RF), smem ~150KB. Measured local optimum — do not perturb.
__global__ __launch_bounds__(NWARP*32, 1)
void main_kernel(const float* __restrict__ p, float* __restrict__ out)
{
    extern __shared__ float dyn[];
    float* w2t = dyn;              // pe_w2 c-quad       4096
    float* w1a = w2t + 4096;       // at_w1 c-quad       4096
    float* w2a = w1a + 4096;       // at_w2 c-quad       4096
    float* pe1 = w2a + 4096;       // 192
    float* bpe = pe1 + 192;        // 64
    float* pb2 = bpe + 64;
    float* s0  = pb2 + 64;
    float* b0  = s0  + 64;
    float* bb1 = b0  + 64;
    float* ab2 = bb1 + 64;
    float* bufs = ab2 + 64;        // [NWARP][2][1024]

    int t = threadIdx.x, lane = t & 31, warp = t >> 5;

    for (int i = t; i < 4096; i += NWARP*32) {
        w2t[i] = g_pe_w2q[i];
        w1a[i] = g_at_w1q[i];
        w2a[i] = g_at_w2q[i];
    }
    if (t < 192) pe1[t] = g_pe_w1f[t];
    if (t >= 192 && t < 256) {
        int c = t - 192;
        bpe[c] = g_b_pef[c]; pb2[c] = g_pe_b2c[c];
        s0[c]  = g_s0[c];    b0[c]  = g_b0[c];
        bb1[c] = g_bb1[c];   ab2[c] = g_at_b2c[c];
    }
    __syncthreads();

    int c0 = lane, c1 = lane + 32;
    float pa0 = pe1[c0*3], pa1 = pe1[c0*3+1], pa2 = pe1[c0*3+2];
    float pq0 = pe1[c1*3], pq1 = pe1[c1*3+1], pq2 = pe1[c1*3+2];
    float bpa = bpe[c0], bpb = bpe[c1];
    float s0a = s0[c0],  s0b = s0[c1];
    float b0a = b0[c0],  b0b = b0[c1];

    float* B0 = bufs + warp*2048;        // h / a1
    float* B2 = B0 + 1024;               // a3

    const int stride = MAIN_GRID * NWARP;
    for (int g = blockIdx.x * NWARP + warp; g < Bz*Nz; g += stride) {
        int b = g >> 12, n = g & 4095;
        const float* pb3 = p + b*Nz*3;
        int bN64 = b*Nz*Cz;

        int idv[Kz];
        #pragma unroll
        for (int k = 0; k < Kz; k++) idv[k] = __ldg(g_idx + g*Kz + k);

        float psx = __ldg(p + g*3), psy = __ldg(p + g*3 + 1), psz = __ldg(p + g*3 + 2);

        // h[k][c] = relu(pe_w1f @ (p - pn) + b_pef)
        #pragma unroll
        for (int k = 0; k < Kz; k++) {
            int id = idv[k];
            float rx = psx - __ldg(pb3 + id*3);
            float ry = psy - __ldg(pb3 + id*3 + 1);
            float rz = psz - __ldg(pb3 + id*3 + 2);
            float h0 = fmaf(pa0, rx, fmaf(pa1, ry, fmaf(pa2, rz, bpa)));
            float h1 = fmaf(pq0, rx, fmaf(pq1, ry, fmaf(pq2, rz, bpb)));
            B0[k*64 + c0] = fmaxf(h0, 0.f);
            B0[k*64 + c1] = fmaxf(h1, 0.f);
        }
        __syncwarp();

        // n_r in registers (lane owns c0, c1 per k)
        float nr0[Kz], nr1[Kz];
        gemv_regs(w2t, B0, pb2, lane, nr0, nr1);
        __syncwarp();

        // a1[k][c] = relu((q - n_k + n_r)*s0 + b0) -> B0
        float qa = __ldg(g_q + g*Cz + c0), qb = __ldg(g_q + g*Cz + c1);
        #pragma unroll
        for (int k = 0; k < Kz; k++) {
            int base = bN64 + idv[k]*Cz;
            float nk0 = __ldg(g_k + base + c0);
            float nk1 = __ldg(g_k + base + c1);
            float a0x = fmaf(qa - nk0 + nr0[k], s0a, b0a);
            float a1x = fmaf(qb - nk1 + nr1[k], s0b, b0b);
            B0[k*64 + c0] = fmaxf(a0x, 0.f);
            B0[k*64 + c1] = fmaxf(a1x, 0.f);
        }
        __syncwarp();

        // a3[k][o] = relu(at_w1' @ a1 + bb1) -> B2
        gemv_smem_relu(w1a, B0, B2, bb1, lane);
        __syncwarp();

        // a4 in registers
        float a40[Kz], a41[Kz];
        gemv_regs(w2a, B2, ab2, lane, a40, a41);

        // softmax over k + aggregate, entirely in registers (mask all-true)
        float* outp = out + Bz*Nz*3 + (b*Cz)*Nz + n;
        {
            float mx0 = -FLT_BIG, mx1 = -FLT_BIG;
            #pragma unroll
            for (int k = 0; k < Kz; k++) { mx0 = fmaxf(mx0, a40[k]); mx1 = fmaxf(mx1, a41[k]); }
            float sA = 0.f, sB = 0.f;
            #pragma unroll
            for (int k = 0; k < Kz; k++) {
                a40[k] = __expf(a40[k] - mx0); sA += a40[k];
                a41[k] = __expf(a41[k] - mx1); sB += a41[k];
            }
            float invA = 1.f / sA, invB = 1.f / sB;
            float y0 = 0.f, y1 = 0.f;
            #pragma unroll
            for (int k = 0; k < Kz; k++) {
                int base = bN64 + idv[k]*Cz;
                float v0 = __ldg(g_v + base + c0);
                float v1 = __ldg(g_v + base + c1);
                y0 = fmaf(a40[k]*invA, v0 + nr0[k], y0);
                y1 = fmaf(a41[k]*invB, v1 + nr1[k], y1);
            }
            outp[c0*Nz] = y0;
            outp[c1*Nz] = y1;
        }
        __syncwarp();
    }
}

// ---------------- launch ----------------
extern "C" void kernel_launch(void* const* d_in, const int* in_sizes, int n_in,
                              void* d_out, int out_size)
{
    const float* p     = (const float*)d_in[0];
    const float* x     = (const float*)d_in[1];
    // d_in[2] = mask, all-true by construction -> unused
    const float* Wq    = (const float*)d_in[3];
    const float* bq    = (const float*)d_in[4];
    const float* Wk    = (const float*)d_in[5];
    const float* bk    = (const float*)d_in[6];
    const float* Wv    = (const float*)d_in[7];
    const float* bv    = (const float*)d_in[8];
    const float* pe_w1 = (const float*)d_in[9];
    const float* pbg   = (const float*)d_in[10];
    const float* pbb   = (const float*)d_in[11];
    const float* pbm   = (const float*)d_in[12];
    const float* pbv   = (const float*)d_in[13];
    const float* pe_w2 = (const float*)d_in[14];
    const float* pe_b2 = (const float*)d_in[15];
    const float* a0g   = (const float*)d_in[16];
    const float* a0b   = (const float*)d_in[17];
    const float* a0m   = (const float*)d_in[18];
    const float* a0v   = (const float*)d_in[19];
    const float* at_w1 = (const float*)d_in[20];
    const float* a1g   = (const float*)d_in[21];
    const float* a1b   = (const float*)d_in[22];
    const float* a1m   = (const float*)d_in[23];
    const float* a1v   = (const float*)d_in[24];
    const float* at_w2 = (const float*)d_in[25];
    const float* at_b2 = (const float*)d_in[26];

    float* out = (float*)d_out;

    const int QKV_SMEM  = QKV_FLOATS * (int)sizeof(float);            // ~69.6KB
    const int MAIN_SMEM = MAIN_FLOATS * (int)sizeof(float);           // ~150KB

    cudaFuncSetAttribute(qkv_fold_kernel, cudaFuncAttributeMaxDynamicSharedMemorySize, QKV_SMEM);
    cudaFuncSetAttribute(main_kernel,     cudaFuncAttributeMaxDynamicSharedMemorySize, MAIN_SMEM);

    qkv_fold_kernel<<<K1_GRID, 256, QKV_SMEM>>>(
        p, out, x, Wq, bq, Wk, bk, Wv, bv,
        pe_w1, pbg, pbb, pbm, pbv, pe_w2, pe_b2,
        a0g, a0b, a0m, a0v, at_w1,
        a1g, a1b, a1m, a1v, at_w2, at_b2);

    knn_kernel<<<Bz*(Nz/KWARPS), KWARPS*32>>>();

    main_kernel<<<MAIN_GRID, NWARP*32, MAIN_SMEM>>>(p, out);
}